// round 3
// baseline (speedup 1.0000x reference)
#include <cuda_runtime.h>

// AutoregressiveNetwork: 63 masked MLPs [B,k]->64->64->2 (+ constant net 0)
// B=16384, DIM=64, HID=64. Output = concat(scales[B,64], translations[B,64]).
//
// Design: one CTA = (network, 128-row batch tile). Weights in SMEM, read via
// broadcast LDS.128. Activations in per-thread SMEM column xs[j][tid] so the
// layer-1 loop can have runtime bound j<k (causal mask -> half the layer-1 work).
// All MACs via Blackwell packed fma.rn.f32x2 (2 fp32 MACs / instruction).

#define BATCHN 16384
#define DIMN   64
#define HIDN   64
#define NNETS  63
#define TPB    128
#define MTILE  128

typedef unsigned long long u64;

// dynamic SMEM layout (float offsets)
#define OFF_W1 0          // 4096 floats
#define OFF_W2 4096       // 4096
#define OFF_XS 8192       // 64*128 = 8192
#define OFF_W3 16384      // 128
#define OFF_B1 16512      // 64
#define OFF_B2 16576      // 64
#define OFF_B3 16640      // 2 (+pad)
#define SMEM_FLOATS 16648
#define SMEM_BYTES (SMEM_FLOATS * 4)

__device__ __forceinline__ u64 pack2(float x) {
    u64 r; asm("mov.b64 %0, {%1, %1};" : "=l"(r) : "f"(x)); return r;
}
__device__ __forceinline__ u64 pk2(float a, float b) {
    u64 r; asm("mov.b64 %0, {%1, %2};" : "=l"(r) : "f"(a), "f"(b)); return r;
}
__device__ __forceinline__ void ffma2(u64& d, u64 a, u64 b) {
    asm("fma.rn.f32x2 %0, %1, %2, %0;" : "+l"(d) : "l"(a), "l"(b));
}
__device__ __forceinline__ float2 un2(u64 a) {
    float2 f; asm("mov.b64 {%0, %1}, %2;" : "=f"(f.x), "=f"(f.y) : "l"(a)); return f;
}

__global__ void __launch_bounds__(TPB)
arnet_kernel(const float* __restrict__ x,
             const float* __restrict__ w0, const float* __restrict__ b0,
             const float* __restrict__ v0, const float* __restrict__ c0,
             const float* __restrict__ W1, const float* __restrict__ B1,
             const float* __restrict__ W2, const float* __restrict__ B2,
             const float* __restrict__ W3, const float* __restrict__ B3,
             float* __restrict__ out)
{
    extern __shared__ float smem[];
    float* w1s = smem + OFF_W1;
    float* w2s = smem + OFF_W2;
    float* xs  = smem + OFF_XS;   // xs[j*TPB + t]
    float* w3s = smem + OFF_W3;
    float* b1s = smem + OFF_B1;
    float* b2s = smem + OFF_B2;
    float* b3s = smem + OFF_B3;

    const int t   = threadIdx.x;
    const int net = blockIdx.y;        // 0..62 -> network index k = net+1
    const int k   = net + 1;           // layer-1 sees x[:, :k]
    const int b   = blockIdx.x * MTILE + t;

    // ---- cooperative weight loads (float4, coalesced) ----
    {
        const float4* gW1 = (const float4*)(W1 + (size_t)net * DIMN * HIDN);
        const float4* gW2 = (const float4*)(W2 + (size_t)net * HIDN * HIDN);
        float4* s1 = (float4*)w1s;
        float4* s2 = (float4*)w2s;
        #pragma unroll
        for (int i = 0; i < 8; i++) {
            s1[t + i * TPB] = gW1[t + i * TPB];
            s2[t + i * TPB] = gW2[t + i * TPB];
        }
        if (t < 32) ((float4*)w3s)[t] = ((const float4*)(W3 + (size_t)net * HIDN * 2))[t];
        if (t < 16) {
            ((float4*)b1s)[t] = ((const float4*)(B1 + (size_t)net * HIDN))[t];
            ((float4*)b2s)[t] = ((const float4*)(B2 + (size_t)net * HIDN))[t];
        }
        if (t == 0) { b3s[0] = B3[net * 2]; b3s[1] = B3[net * 2 + 1]; }
    }

    // ---- stage this thread's x row into its SMEM column ----
    {
        const float4* xr = (const float4*)(x + (size_t)b * DIMN);
        #pragma unroll
        for (int q = 0; q < 16; q++) {
            float4 v = xr[q];
            xs[(4 * q + 0) * TPB + t] = v.x;
            xs[(4 * q + 1) * TPB + t] = v.y;
            xs[(4 * q + 2) * TPB + t] = v.z;
            xs[(4 * q + 3) * TPB + t] = v.w;
        }
    }
    __syncthreads();

    u64 acc[32];

    // ---- layer 1: h1 = relu(x[:, :k] @ W1[net, :k, :] + B1) ----
    #pragma unroll
    for (int h = 0; h < 32; h++) acc[h] = ((const u64*)b1s)[h];
    #pragma unroll 4
    for (int j = 0; j < k; j++) {                      // runtime bound = causal mask
        u64 xv = pack2(xs[j * TPB + t]);
        const ulonglong2* row = (const ulonglong2*)(w1s + j * HIDN);
        #pragma unroll
        for (int q = 0; q < 16; q++) {
            ulonglong2 w = row[q];                     // broadcast LDS.128
            ffma2(acc[2 * q],     xv, w.x);
            ffma2(acc[2 * q + 1], xv, w.y);
        }
    }
    #pragma unroll
    for (int h = 0; h < 32; h++) {
        float2 f = un2(acc[h]);
        xs[(2 * h) * TPB + t]     = fmaxf(f.x, 0.0f);  // each thread owns its column:
        xs[(2 * h + 1) * TPB + t] = fmaxf(f.y, 0.0f);  // no __syncthreads needed
    }

    // ---- layer 2: h2 = relu(h1 @ W2[net] + B2) ----
    #pragma unroll
    for (int h = 0; h < 32; h++) acc[h] = ((const u64*)b2s)[h];
    #pragma unroll 4
    for (int j = 0; j < HIDN; j++) {
        u64 xv = pack2(xs[j * TPB + t]);
        const ulonglong2* row = (const ulonglong2*)(w2s + j * HIDN);
        #pragma unroll
        for (int q = 0; q < 16; q++) {
            ulonglong2 w = row[q];
            ffma2(acc[2 * q],     xv, w.x);
            ffma2(acc[2 * q + 1], xv, w.y);
        }
    }

    // ---- layer 3: (scale, trans) = relu(h2) @ W3[net] + B3 ----
    u64 o = ((const u64*)b3s)[0];
    #pragma unroll
    for (int h = 0; h < 32; h++) {
        float2 f = un2(acc[h]);
        ffma2(o, pack2(fmaxf(f.x, 0.0f)), ((const u64*)w3s)[2 * h]);
        ffma2(o, pack2(fmaxf(f.y, 0.0f)), ((const u64*)w3s)[2 * h + 1]);
    }
    float2 ot = un2(o);
    float s = fminf(fmaxf(ot.x, -5.0f), 5.0f);
    out[(size_t)b * DIMN + k]                    = s;     // scales[b, k]
    out[(size_t)(BATCHN + b) * DIMN + k]         = ot.y;  // translations[b, k]

    // ---- network 0: constant column (computed redundantly, trivial cost) ----
    if (net == 0) {
        float s0 = c0[0], t0 = c0[1];
        #pragma unroll
        for (int h = 0; h < HIDN; h++) {
            float h0 = fmaxf(w0[h] + b0[h], 0.0f);
            s0 = fmaf(h0, v0[2 * h],     s0);
            t0 = fmaf(h0, v0[2 * h + 1], t0);
        }
        s0 = fminf(fmaxf(s0, -5.0f), 5.0f);
        out[(size_t)b * DIMN]            = s0;
        out[(size_t)(BATCHN + b) * DIMN] = t0;
    }
}

extern "C" void kernel_launch(void* const* d_in, const int* in_sizes, int n_in,
                              void* d_out, int out_size)
{
    (void)in_sizes; (void)n_in; (void)out_size;
    const float* x  = (const float*)d_in[0];
    const float* w0 = (const float*)d_in[1];
    const float* b0 = (const float*)d_in[2];
    const float* v0 = (const float*)d_in[3];
    const float* c0 = (const float*)d_in[4];
    const float* W1 = (const float*)d_in[5];
    const float* B1 = (const float*)d_in[6];
    const float* W2 = (const float*)d_in[7];
    const float* B2 = (const float*)d_in[8];
    const float* W3 = (const float*)d_in[9];
    const float* B3 = (const float*)d_in[10];
    float* out = (float*)d_out;

    cudaFuncSetAttribute(arnet_kernel,
                         cudaFuncAttributeMaxDynamicSharedMemorySize, SMEM_BYTES);

    dim3 grid(BATCHN / MTILE, NNETS);   // (128, 63)
    arnet_kernel<<<grid, TPB, SMEM_BYTES>>>(x, w0, b0, v0, c0,
                                            W1, B1, W2, B2, W3, B3, out);
}

// round 5
// speedup vs baseline: 1.1291x; 1.1291x over previous
#include <cuda_runtime.h>

// AutoregressiveNetwork: 63 masked MLPs [B,k]->64->64->2 (+ constant net 0)
// B=16384, DIM=64, HID=64. Output = concat(scales[B,64], translations[B,64]).
//
// R3 design: GEMM register tiling. CTA = (net, 128-row tile). 128 threads as
// 16x8: each thread owns an 8x8 micro-tile (acc pairs along rows as f32x2).
// Per K-step: 4 conflict-free LDS.128 + 32 FFMA2 (vs 17 LDS : 32 FFMA2 in R2,
// which pinned l1tex at 95%). Activations column-major in SMEM; H1 written
// back transposed into the same buffer. FLOPs via Blackwell fma.rn.f32x2.

#define BATCHN 16384
#define DIMN   64
#define HIDN   64
#define NNETS  63
#define TPB    128
#define XS     128          // column stride of activation buffer XH[col][row]

typedef unsigned long long u64;

// dynamic SMEM layout (float offsets)
#define OFF_XH 0            // 64*128 = 8192  (x tile, then reused for relu(h1))
#define OFF_W1 8192         // 4096  (also reused as L3 reduction buffer)
#define OFF_W2 12288        // 4096
#define OFF_W3 16384        // 128
#define OFF_B1 16512        // 64
#define OFF_B2 16576        // 64
#define OFF_B3 16640        // 2 (+pad)
#define SMEM_FLOATS 16648
#define SMEM_BYTES (SMEM_FLOATS * 4)

__device__ __forceinline__ u64 pack2(float x) {
    u64 r; asm("mov.b64 %0, {%1, %1};" : "=l"(r) : "f"(x)); return r;
}
__device__ __forceinline__ u64 pk2(float a, float b) {
    u64 r; asm("mov.b64 %0, {%1, %2};" : "=l"(r) : "f"(a), "f"(b)); return r;
}
__device__ __forceinline__ void ffma2(u64& d, u64 a, u64 b) {
    asm("fma.rn.f32x2 %0, %1, %2, %0;" : "+l"(d) : "l"(a), "l"(b));
}
__device__ __forceinline__ void add2(u64& d, u64 a) {
    asm("add.rn.f32x2 %0, %0, %1;" : "+l"(d) : "l"(a));
}
__device__ __forceinline__ float2 un2(u64 a) {
    float2 f; asm("mov.b64 {%0, %1}, %2;" : "=f"(f.x), "=f"(f.y) : "l"(a)); return f;
}

__global__ void __launch_bounds__(TPB, 3)
arnet_kernel(const float* __restrict__ x,
             const float* __restrict__ w0, const float* __restrict__ b0,
             const float* __restrict__ v0, const float* __restrict__ c0,
             const float* __restrict__ W1, const float* __restrict__ B1,
             const float* __restrict__ W2, const float* __restrict__ B2,
             const float* __restrict__ W3, const float* __restrict__ B3,
             float* __restrict__ out)
{
    extern __shared__ float sm[];
    float* XH  = sm + OFF_XH;     // XH[col*XS + row]
    float* W1s = sm + OFF_W1;     // [j][col] row-major
    float* W2s = sm + OFF_W2;
    float* W3s = sm + OFF_W3;     // [col][2]
    float* B1s = sm + OFF_B1;
    float* B2s = sm + OFF_B2;
    float* B3s = sm + OFF_B3;

    const int t  = threadIdx.x;
    const int r  = t >> 3;        // 0..15
    const int c  = t & 7;         // 0..7
    const int R0 = r * 8;         // this thread's 8 batch rows (within tile)
    const int C0 = c * 8;         // this thread's 8 hidden cols
    const int net  = blockIdx.y;  // 0..62 -> network k = net+1
    const int k    = net + 1;     // layer-1 causal width
    const int brow = blockIdx.x * TPB + t;

    // ---- stage weights (coalesced float4 copies) ----
    {
        const float4* g1 = (const float4*)(W1 + (size_t)net * 4096);
        const float4* g2 = (const float4*)(W2 + (size_t)net * 4096);
        #pragma unroll
        for (int i = 0; i < 8; i++) {
            ((float4*)W1s)[t + i * TPB] = g1[t + i * TPB];
            ((float4*)W2s)[t + i * TPB] = g2[t + i * TPB];
        }
        W3s[t] = W3[(size_t)net * 128 + t];
        if (t < 64) { B1s[t] = B1[net * 64 + t]; B2s[t] = B2[net * 64 + t]; }
        if (t == 0) { B3s[0] = B3[net * 2]; B3s[1] = B3[net * 2 + 1]; }
    }

    // ---- stage x tile column-major: XH[col][row] (conflict-free STS) ----
    {
        const float4* xr = (const float4*)(x + (size_t)brow * DIMN);
        #pragma unroll
        for (int q = 0; q < 16; q++) {
            float4 v = xr[q];
            XH[(4 * q + 0) * XS + t] = v.x;
            XH[(4 * q + 1) * XS + t] = v.y;
            XH[(4 * q + 2) * XS + t] = v.z;
            XH[(4 * q + 3) * XS + t] = v.w;
        }
    }
    __syncthreads();

    u64 acc[32];   // acc[i2*8+q]: rows (R0+2*i2, R0+2*i2+1), col C0+q

    // ================= layer 1: relu(x[:, :k] @ W1 + B1) =================
    #pragma unroll
    for (int q = 0; q < 8; q++) {
        u64 bb = pack2(B1s[C0 + q]);
        #pragma unroll
        for (int i2 = 0; i2 < 4; i2++) acc[i2 * 8 + q] = bb;
    }
    #pragma unroll 2
    for (int j = 0; j < k; j++) {                 // runtime bound = causal mask
        u64 a0 = *(const u64*)&XH[j * XS + R0 + 0];
        u64 a1 = *(const u64*)&XH[j * XS + R0 + 2];
        u64 a2 = *(const u64*)&XH[j * XS + R0 + 4];
        u64 a3 = *(const u64*)&XH[j * XS + R0 + 6];
        float4 bv0 = *(const float4*)&W1s[j * 64 + C0];
        float4 bv1 = *(const float4*)&W1s[j * 64 + C0 + 4];
        u64 w[8];
        w[0] = pack2(bv0.x); w[1] = pack2(bv0.y); w[2] = pack2(bv0.z); w[3] = pack2(bv0.w);
        w[4] = pack2(bv1.x); w[5] = pack2(bv1.y); w[6] = pack2(bv1.z); w[7] = pack2(bv1.w);
        #pragma unroll
        for (int q = 0; q < 8; q++) {
            ffma2(acc[0 * 8 + q], a0, w[q]);
            ffma2(acc[1 * 8 + q], a1, w[q]);
            ffma2(acc[2 * 8 + q], a2, w[q]);
            ffma2(acc[3 * 8 + q], a3, w[q]);
        }
    }
    __syncthreads();   // all threads done reading XH before overwrite

    // relu + store H1 transposed back into XH (one-time; minor bank conflicts)
    #pragma unroll
    for (int q = 0; q < 8; q++) {
        #pragma unroll
        for (int i2 = 0; i2 < 4; i2++) {
            float2 f = un2(acc[i2 * 8 + q]);
            *(u64*)&XH[(C0 + q) * XS + R0 + 2 * i2] =
                pk2(fmaxf(f.x, 0.0f), fmaxf(f.y, 0.0f));
        }
    }
    __syncthreads();

    // ================= layer 2: relu(h1 @ W2 + B2) =================
    #pragma unroll
    for (int q = 0; q < 8; q++) {
        u64 bb = pack2(B2s[C0 + q]);
        #pragma unroll
        for (int i2 = 0; i2 < 4; i2++) acc[i2 * 8 + q] = bb;
    }
    #pragma unroll 2
    for (int j = 0; j < HIDN; j++) {
        u64 a0 = *(const u64*)&XH[j * XS + R0 + 0];
        u64 a1 = *(const u64*)&XH[j * XS + R0 + 2];
        u64 a2 = *(const u64*)&XH[j * XS + R0 + 4];
        u64 a3 = *(const u64*)&XH[j * XS + R0 + 6];
        float4 bv0 = *(const float4*)&W2s[j * 64 + C0];
        float4 bv1 = *(const float4*)&W2s[j * 64 + C0 + 4];
        u64 w[8];
        w[0] = pack2(bv0.x); w[1] = pack2(bv0.y); w[2] = pack2(bv0.z); w[3] = pack2(bv0.w);
        w[4] = pack2(bv1.x); w[5] = pack2(bv1.y); w[6] = pack2(bv1.z); w[7] = pack2(bv1.w);
        #pragma unroll
        for (int q = 0; q < 8; q++) {
            ffma2(acc[0 * 8 + q], a0, w[q]);
            ffma2(acc[1 * 8 + q], a1, w[q]);
            ffma2(acc[2 * 8 + q], a2, w[q]);
            ffma2(acc[3 * 8 + q], a3, w[q]);
        }
    }

    // ================= layer 3: relu(h2) @ W3 + B3 =================
    // per-thread partials over this thread's 8 cols; po[e] = (out0,out1) pair
    u64 po[8];
    #pragma unroll
    for (int e = 0; e < 8; e++) po[e] = 0ULL;
    #pragma unroll
    for (int q = 0; q < 8; q++) {
        u64 w3 = *(const u64*)&W3s[(C0 + q) * 2];
        #pragma unroll
        for (int i2 = 0; i2 < 4; i2++) {
            float2 f = un2(acc[i2 * 8 + q]);
            ffma2(po[2 * i2 + 0], pack2(fmaxf(f.x, 0.0f)), w3);
            ffma2(po[2 * i2 + 1], pack2(fmaxf(f.y, 0.0f)), w3);
        }
    }
    // cross-thread (over c) reduction through SMEM overlaid on W1s
    u64* redU = (u64*)W1s;            // [128 rows][stride 9] of (out0,out1)
    #pragma unroll
    for (int e = 0; e < 8; e++) redU[(R0 + e) * 9 + c] = po[e];
    __syncthreads();
    {
        u64 s = redU[t * 9 + 0];
        #pragma unroll
        for (int cc = 1; cc < 8; cc++) add2(s, redU[t * 9 + cc]);
        float2 f = un2(s);
        float sc = fminf(fmaxf(f.x + B3s[0], -5.0f), 5.0f);
        float tr = f.y + B3s[1];
        out[(size_t)brow * DIMN + k]            = sc;   // scales[brow, k]
        out[(size_t)(BATCHN + brow) * DIMN + k] = tr;   // translations[brow, k]
    }

    // ---- network 0: constant column (only the net==0 CTAs do this) ----
    if (net == 0) {
        float s0 = c0[0], t0 = c0[1];
        #pragma unroll
        for (int h = 0; h < HIDN; h++) {
            float h0 = fmaxf(w0[h] + b0[h], 0.0f);
            s0 = fmaf(h0, v0[2 * h],     s0);
            t0 = fmaf(h0, v0[2 * h + 1], t0);
        }
        s0 = fminf(fmaxf(s0, -5.0f), 5.0f);
        out[(size_t)brow * DIMN]            = s0;
        out[(size_t)(BATCHN + brow) * DIMN] = t0;
    }
}

extern "C" void kernel_launch(void* const* d_in, const int* in_sizes, int n_in,
                              void* d_out, int out_size)
{
    (void)in_sizes; (void)n_in; (void)out_size;
    const float* x  = (const float*)d_in[0];
    const float* w0 = (const float*)d_in[1];
    const float* b0 = (const float*)d_in[2];
    const float* v0 = (const float*)d_in[3];
    const float* c0 = (const float*)d_in[4];
    const float* W1 = (const float*)d_in[5];
    const float* B1 = (const float*)d_in[6];
    const float* W2 = (const float*)d_in[7];
    const float* B2 = (const float*)d_in[8];
    const float* W3 = (const float*)d_in[9];
    const float* B3 = (const float*)d_in[10];
    float* out = (float*)d_out;

    cudaFuncSetAttribute(arnet_kernel,
                         cudaFuncAttributeMaxDynamicSharedMemorySize, SMEM_BYTES);

    dim3 grid(BATCHN / TPB, NNETS);   // (128, 63)
    arnet_kernel<<<grid, TPB, SMEM_BYTES>>>(x, w0, b0, v0, c0,
                                            W1, B1, W2, B2, W3, B3, out);
}

// round 7
// speedup vs baseline: 1.8544x; 1.6423x over previous
#include <cuda_runtime.h>
#include <cuda_bf16.h>
#include <cstdint>

// AutoregressiveNetwork via warp-level HMMA (mma.sync m16n8k16 bf16, sm_80+ PTX
// -- tcgen05 is unavailable because the harness emits compute_103 PTX).
// 63 masked MLPs [B,k]->64->64->2, B=16384. CTA = (net, 128-row tile), 4 warps,
// each warp owns 32 rows x 64 cols. 3-pass bf16 hi/lo split, fp32 accumulators.
// Layer1 -> Layer2 chains in registers: D-fragment layout == A-fragment layout.

#define BATCHN 16384
#define TPB    128

// SMEM layout. Row stride 144B (36 words): bank(lane) = 4*(l/4)+(l%4) = l,
// conflict-free for both A-fragment and B-fragment LDS patterns.
#define ASTR   144
#define SO_AHI 0          // x hi : 128 rows * 144B = 18432
#define SO_ALO 18432      // x lo
#define SO_W1H 36864      // W1^T hi : 64 rows * 144B = 9216  ([n][j], j masked >= k)
#define SO_W1L 46080
#define SO_W2H 55296
#define SO_W2L 64512
#define SO_W3  73728      // 64 x float2 (out0,out1)
#define SO_B1  74240      // 64 floats
#define SO_B2  74496      // 64 floats
#define SO_B3  74752      // float2
#define SMEM_BYTES 74768

typedef unsigned long long u64;

// ---- f32x2 helpers (layer-3 epilogue) ----
static __device__ __forceinline__ u64 pack2(float x) {
    u64 r; asm("mov.b64 %0, {%1, %1};" : "=l"(r) : "f"(x)); return r;
}
static __device__ __forceinline__ void ffma2(u64& d, u64 a, u64 b) {
    asm("fma.rn.f32x2 %0, %1, %2, %0;" : "+l"(d) : "l"(a), "l"(b));
}
static __device__ __forceinline__ float2 un2(u64 a) {
    float2 f; asm("mov.b64 {%0, %1}, %2;" : "=f"(f.x), "=f"(f.y) : "l"(a)); return f;
}

// ---- bf16 hi/lo split ----
static __device__ __forceinline__ void split1(float v, __nv_bfloat16& h, __nv_bfloat16& l) {
    h = __float2bfloat16_rn(v);
    l = __float2bfloat16_rn(v - __bfloat162float(h));
}
// pack (a -> low half, b -> high half); matches mma fragment element order
static __device__ __forceinline__ void split2p(float a, float b, uint32_t& hp, uint32_t& lp) {
    __nv_bfloat16 ha, la, hb, lb;
    split1(a, ha, la); split1(b, hb, lb);
    hp = ((uint32_t)*(unsigned short*)&hb << 16) | *(unsigned short*)&ha;
    lp = ((uint32_t)*(unsigned short*)&lb << 16) | *(unsigned short*)&la;
}

// mma.sync m16n8k16 row.col f32 += bf16*bf16
static __device__ __forceinline__ void mma16816(float* d, const uint32_t* a,
                                                uint32_t b0, uint32_t b1) {
    asm volatile(
        "mma.sync.aligned.m16n8k16.row.col.f32.bf16.bf16.f32 "
        "{%0,%1,%2,%3}, {%4,%5,%6,%7}, {%8,%9}, {%0,%1,%2,%3};"
        : "+f"(d[0]), "+f"(d[1]), "+f"(d[2]), "+f"(d[3])
        : "r"(a[0]), "r"(a[1]), "r"(a[2]), "r"(a[3]), "r"(b0), "r"(b1));
}

__global__ void __launch_bounds__(TPB, 2)
arnet_hmma(const float* __restrict__ x,
           const float* __restrict__ w0, const float* __restrict__ b0,
           const float* __restrict__ v0, const float* __restrict__ c0,
           const float* __restrict__ W1, const float* __restrict__ B1,
           const float* __restrict__ W2, const float* __restrict__ B2,
           const float* __restrict__ W3, const float* __restrict__ B3,
           float* __restrict__ out)
{
    extern __shared__ char smc[];
    const int t    = threadIdx.x;
    const int lane = t & 31;
    const int wrp  = t >> 5;
    const int qr   = lane >> 2;      // 0..7
    const int qc   = lane & 3;       // 0..3
    const int net  = blockIdx.y;     // network index k = net+1
    const int k    = net + 1;
    const int brow0 = blockIdx.x * TPB;

    // ---- stage x tile -> bf16 hi/lo, [row][col], 144B row stride ----
    {
        const float4* gx = (const float4*)(x + (size_t)brow0 * 64);
        #pragma unroll
        for (int i = 0; i < 16; i++) {
            int idx = t + i * TPB;           // 0..2047 float4s
            int r = idx >> 4, q = idx & 15;  // row, quad-col
            float4 v = gx[idx];
            uint32_t h01, l01, h23, l23;
            split2p(v.x, v.y, h01, l01);
            split2p(v.z, v.w, h23, l23);
            *(uint2*)(smc + SO_AHI + r * ASTR + q * 8) = make_uint2(h01, h23);
            *(uint2*)(smc + SO_ALO + r * ASTR + q * 8) = make_uint2(l01, l23);
        }
    }
    // ---- stage W1^T (masked j>=k) and W2^T as [n][j] bf16 hi/lo ----
    {
        const float4* g1 = (const float4*)(W1 + (size_t)net * 4096);
        const float4* g2 = (const float4*)(W2 + (size_t)net * 4096);
        #pragma unroll
        for (int i = 0; i < 8; i++) {
            int i4 = t + i * TPB;            // 0..1023 float4s; elem = (j, n0..n0+3)
            int j = i4 >> 4, n0 = (i4 & 15) * 4;
            float4 v1 = g1[i4];
            float4 v2 = g2[i4];
            if (j >= k) { v1.x = v1.y = v1.z = v1.w = 0.0f; }   // causal mask
            float e1[4] = {v1.x, v1.y, v1.z, v1.w};
            float e2[4] = {v2.x, v2.y, v2.z, v2.w};
            #pragma unroll
            for (int e = 0; e < 4; e++) {
                __nv_bfloat16 h, l;
                int off = (n0 + e) * ASTR + j * 2;
                split1(e1[e], h, l);
                *(__nv_bfloat16*)(smc + SO_W1H + off) = h;
                *(__nv_bfloat16*)(smc + SO_W1L + off) = l;
                split1(e2[e], h, l);
                *(__nv_bfloat16*)(smc + SO_W2H + off) = h;
                *(__nv_bfloat16*)(smc + SO_W2L + off) = l;
            }
        }
        if (t < 64) {
            ((float*)(smc + SO_B1))[t] = B1[net * 64 + t];
            ((float*)(smc + SO_B2))[t] = B2[net * 64 + t];
            ((float2*)(smc + SO_W3))[t] =
                make_float2(W3[(size_t)net * 128 + 2 * t], W3[(size_t)net * 128 + 2 * t + 1]);
        }
        if (t == 0)
            *((float2*)(smc + SO_B3)) = make_float2(B3[net * 2], B3[net * 2 + 1]);
    }
    __syncthreads();

    const char* Ah  = smc + SO_AHI;
    const char* Al  = smc + SO_ALO;
    const char* Wh1 = smc + SO_W1H;
    const char* Wl1 = smc + SO_W1L;
    const char* Wh2 = smc + SO_W2H;
    const char* Wl2 = smc + SO_W2L;

    // ================= layer 1: D1 = x @ W1m + B1 (3-pass) =================
    float D1[2][8][4];
    {
        const float* b1s = (const float*)(smc + SO_B1);
        #pragma unroll
        for (int n = 0; n < 8; n++) {
            float bx = b1s[n * 8 + qc * 2], by = b1s[n * 8 + qc * 2 + 1];
            #pragma unroll
            for (int m = 0; m < 2; m++) {
                D1[m][n][0] = bx; D1[m][n][1] = by;
                D1[m][n][2] = bx; D1[m][n][3] = by;
            }
        }
    }
    const int kt1 = (k + 15) >> 4;            // causal trim: <= ceil(k/16) k-tiles
    for (int kt = 0; kt < kt1; kt++) {
        uint32_t ah[2][4], al[2][4];
        #pragma unroll
        for (int m = 0; m < 2; m++) {
            int r  = wrp * 32 + m * 16 + qr;
            int cb = qc * 4 + kt * 32;        // byte offset of col pair
            ah[m][0] = *(const uint32_t*)(Ah + r * ASTR + cb);
            ah[m][1] = *(const uint32_t*)(Ah + (r + 8) * ASTR + cb);
            ah[m][2] = *(const uint32_t*)(Ah + r * ASTR + cb + 16);
            ah[m][3] = *(const uint32_t*)(Ah + (r + 8) * ASTR + cb + 16);
            al[m][0] = *(const uint32_t*)(Al + r * ASTR + cb);
            al[m][1] = *(const uint32_t*)(Al + (r + 8) * ASTR + cb);
            al[m][2] = *(const uint32_t*)(Al + r * ASTR + cb + 16);
            al[m][3] = *(const uint32_t*)(Al + (r + 8) * ASTR + cb + 16);
        }
        #pragma unroll
        for (int n = 0; n < 8; n++) {
            int nb = (n * 8 + qr) * ASTR + qc * 4 + kt * 32;
            uint32_t bh0 = *(const uint32_t*)(Wh1 + nb);
            uint32_t bh1 = *(const uint32_t*)(Wh1 + nb + 16);
            uint32_t bl0 = *(const uint32_t*)(Wl1 + nb);
            uint32_t bl1 = *(const uint32_t*)(Wl1 + nb + 16);
            #pragma unroll
            for (int m = 0; m < 2; m++) {
                mma16816(D1[m][n], ah[m], bh0, bh1);
                mma16816(D1[m][n], al[m], bh0, bh1);
                mma16816(D1[m][n], ah[m], bl0, bl1);
            }
        }
    }

    // ================= layer 2: D2 = relu(D1) @ W2 + B2 (in registers) =========
    float D2[2][8][4];
    {
        const float* b2s = (const float*)(smc + SO_B2);
        #pragma unroll
        for (int n = 0; n < 8; n++) {
            float bx = b2s[n * 8 + qc * 2], by = b2s[n * 8 + qc * 2 + 1];
            #pragma unroll
            for (int m = 0; m < 2; m++) {
                D2[m][n][0] = bx; D2[m][n][1] = by;
                D2[m][n][2] = bx; D2[m][n][3] = by;
            }
        }
    }
    #pragma unroll
    for (int kt = 0; kt < 4; kt++) {
        // A-fragment for k-tile kt == D-fragments of n-tiles {2kt, 2kt+1}
        uint32_t ah[2][4], al[2][4];
        #pragma unroll
        for (int m = 0; m < 2; m++) {
            split2p(fmaxf(D1[m][2*kt  ][0], 0.f), fmaxf(D1[m][2*kt  ][1], 0.f), ah[m][0], al[m][0]);
            split2p(fmaxf(D1[m][2*kt  ][2], 0.f), fmaxf(D1[m][2*kt  ][3], 0.f), ah[m][1], al[m][1]);
            split2p(fmaxf(D1[m][2*kt+1][0], 0.f), fmaxf(D1[m][2*kt+1][1], 0.f), ah[m][2], al[m][2]);
            split2p(fmaxf(D1[m][2*kt+1][2], 0.f), fmaxf(D1[m][2*kt+1][3], 0.f), ah[m][3], al[m][3]);
        }
        #pragma unroll
        for (int n = 0; n < 8; n++) {
            int nb = (n * 8 + qr) * ASTR + qc * 4 + kt * 32;
            uint32_t bh0 = *(const uint32_t*)(Wh2 + nb);
            uint32_t bh1 = *(const uint32_t*)(Wh2 + nb + 16);
            uint32_t bl0 = *(const uint32_t*)(Wl2 + nb);
            uint32_t bl1 = *(const uint32_t*)(Wl2 + nb + 16);
            #pragma unroll
            for (int m = 0; m < 2; m++) {
                mma16816(D2[m][n], ah[m], bh0, bh1);
                mma16816(D2[m][n], al[m], bh0, bh1);
                mma16816(D2[m][n], ah[m], bl0, bl1);
            }
        }
    }

    // ================= layer 3: (scale, trans) = relu(D2) @ W3 + B3 ============
    {
        const u64* w3p = (const u64*)(smc + SO_W3);   // (out0,out1) per hidden col
        u64 po[4] = {0ULL, 0ULL, 0ULL, 0ULL};         // rows: m*2 + {0 (r), 1 (r+8)}
        #pragma unroll
        for (int n = 0; n < 8; n++) {
            u64 wa = w3p[n * 8 + qc * 2];
            u64 wb = w3p[n * 8 + qc * 2 + 1];
            #pragma unroll
            for (int m = 0; m < 2; m++) {
                ffma2(po[m * 2 + 0], pack2(fmaxf(D2[m][n][0], 0.f)), wa);
                ffma2(po[m * 2 + 0], pack2(fmaxf(D2[m][n][1], 0.f)), wb);
                ffma2(po[m * 2 + 1], pack2(fmaxf(D2[m][n][2], 0.f)), wa);
                ffma2(po[m * 2 + 1], pack2(fmaxf(D2[m][n][3], 0.f)), wb);
            }
        }
        const float2 b3 = *(const float2*)(smc + SO_B3);
        #pragma unroll
        for (int i = 0; i < 4; i++) {
            float2 f = un2(po[i]);
            f.x += __shfl_xor_sync(0xffffffffu, f.x, 1);
            f.y += __shfl_xor_sync(0xffffffffu, f.y, 1);
            f.x += __shfl_xor_sync(0xffffffffu, f.x, 2);
            f.y += __shfl_xor_sync(0xffffffffu, f.y, 2);
            if (qc == 0) {
                int m = i >> 1, h = i & 1;
                int brow = brow0 + wrp * 32 + m * 16 + h * 8 + qr;
                out[(size_t)brow * 64 + k] = fminf(fmaxf(f.x + b3.x, -5.0f), 5.0f);
                out[(size_t)(BATCHN + brow) * 64 + k] = f.y + b3.y;
            }
        }
    }

    // ---- network 0: constant column (only net==0 CTAs) ----
    if (net == 0) {
        float s0 = c0[0], t0 = c0[1];
        #pragma unroll
        for (int h = 0; h < 64; h++) {
            float hv = fmaxf(w0[h] + b0[h], 0.0f);
            s0 = fmaf(hv, v0[2 * h],     s0);
            t0 = fmaf(hv, v0[2 * h + 1], t0);
        }
        const int brow = brow0 + t;
        out[(size_t)brow * 64] = fminf(fmaxf(s0, -5.0f), 5.0f);
        out[(size_t)(BATCHN + brow) * 64] = t0;
    }
}

extern "C" void kernel_launch(void* const* d_in, const int* in_sizes, int n_in,
                              void* d_out, int out_size)
{
    (void)in_sizes; (void)n_in; (void)out_size;
    const float* x  = (const float*)d_in[0];
    const float* w0 = (const float*)d_in[1];
    const float* b0 = (const float*)d_in[2];
    const float* v0 = (const float*)d_in[3];
    const float* c0 = (const float*)d_in[4];
    const float* W1 = (const float*)d_in[5];
    const float* B1 = (const float*)d_in[6];
    const float* W2 = (const float*)d_in[7];
    const float* B2 = (const float*)d_in[8];
    const float* W3 = (const float*)d_in[9];
    const float* B3 = (const float*)d_in[10];
    float* out = (float*)d_out;

    cudaFuncSetAttribute(arnet_hmma,
                         cudaFuncAttributeMaxDynamicSharedMemorySize, SMEM_BYTES);

    dim3 grid(BATCHN / TPB, 63);   // (128, 63)
    arnet_hmma<<<grid, TPB, SMEM_BYTES>>>(x, w0, b0, v0, c0,
                                          W1, B1, W2, B2, W3, B3, out);
}

// round 9
// speedup vs baseline: 1.9785x; 1.0669x over previous
#include <cuda_runtime.h>
#include <cuda_bf16.h>
#include <cstdint>

// AutoregressiveNetwork via HMMA mma.sync m16n8k16 bf16 + ldmatrix (sm_80 PTX;
// tcgen05 unavailable: harness emits compute_103, not 103a).
// 63 masked MLPs [B,k]->64->64->2, B=16384. CTA = (net, 128-row tile), 4 warps.
// R8: ldmatrix fragment feeds (x4 for A, x4.trans for B so W keeps its native
// [j][n] gmem layout -> staging is a straight bf16 copy), 16-row m-block loop
// through all layers to halve accumulator registers, 128B swizzled rows ->
// 65KB SMEM -> 3 CTAs/SM. 3-pass bf16 hi/lo split, fp32 accum.

#define BATCHN 16384
#define TPB    128

#define SO_XH  0         // x hi : 128 rows * 128B = 16384
#define SO_XL  16384
#define SO_W1H 32768     // W1 [j][n] bf16, 64 rows * 128B = 8192 (j>=k zeroed)
#define SO_W1L 40960
#define SO_W2H 49152
#define SO_W2L 57344
#define SO_W3  65536     // 64 x float2
#define SO_B1  66048     // 64 floats
#define SO_B2  66304
#define SO_B3  66560     // float2
#define SMEM_BYTES 66568

#define SW(o) ((o) ^ (((o) >> 3) & 0x70))   // SW128 swizzle (128B rows)

typedef unsigned long long u64;

static __device__ __forceinline__ uint32_t smem_u32(const void* p) {
    uint32_t a;
    asm("{ .reg .u64 t; cvta.to.shared.u64 t, %1; cvt.u32.u64 %0, t; }" : "=r"(a) : "l"(p));
    return a;
}
static __device__ __forceinline__ u64 pack2(float x) {
    u64 r; asm("mov.b64 %0, {%1, %1};" : "=l"(r) : "f"(x)); return r;
}
static __device__ __forceinline__ void ffma2(u64& d, u64 a, u64 b) {
    asm("fma.rn.f32x2 %0, %1, %2, %0;" : "+l"(d) : "l"(a), "l"(b));
}
static __device__ __forceinline__ float2 un2(u64 a) {
    float2 f; asm("mov.b64 {%0, %1}, %2;" : "=f"(f.x), "=f"(f.y) : "l"(a)); return f;
}
static __device__ __forceinline__ void split1(float v, __nv_bfloat16& h, __nv_bfloat16& l) {
    h = __float2bfloat16_rn(v);
    l = __float2bfloat16_rn(v - __bfloat162float(h));
}
static __device__ __forceinline__ void split2p(float a, float b, uint32_t& hp, uint32_t& lp) {
    __nv_bfloat16 ha, la, hb, lb;
    split1(a, ha, la); split1(b, hb, lb);
    hp = ((uint32_t)*(unsigned short*)&hb << 16) | *(unsigned short*)&ha;
    lp = ((uint32_t)*(unsigned short*)&lb << 16) | *(unsigned short*)&la;
}
static __device__ __forceinline__ void mma16816(float* d, const uint32_t* a,
                                                uint32_t b0, uint32_t b1) {
    asm volatile(
        "mma.sync.aligned.m16n8k16.row.col.f32.bf16.bf16.f32 "
        "{%0,%1,%2,%3}, {%4,%5,%6,%7}, {%8,%9}, {%0,%1,%2,%3};"
        : "+f"(d[0]), "+f"(d[1]), "+f"(d[2]), "+f"(d[3])
        : "r"(a[0]), "r"(a[1]), "r"(a[2]), "r"(a[3]), "r"(b0), "r"(b1));
}
static __device__ __forceinline__ void ldsm_x4(uint32_t* r, uint32_t addr) {
    asm volatile("ldmatrix.sync.aligned.m8n8.x4.shared.b16 {%0,%1,%2,%3}, [%4];"
        : "=r"(r[0]), "=r"(r[1]), "=r"(r[2]), "=r"(r[3]) : "r"(addr));
}
static __device__ __forceinline__ void ldsm_x4t(uint32_t* r, uint32_t addr) {
    asm volatile("ldmatrix.sync.aligned.m8n8.x4.trans.shared.b16 {%0,%1,%2,%3}, [%4];"
        : "=r"(r[0]), "=r"(r[1]), "=r"(r[2]), "=r"(r[3]) : "r"(addr));
}

__global__ void __launch_bounds__(TPB, 3)
arnet_hmma2(const float* __restrict__ x,
            const float* __restrict__ w0, const float* __restrict__ b0,
            const float* __restrict__ v0, const float* __restrict__ c0,
            const float* __restrict__ W1, const float* __restrict__ B1,
            const float* __restrict__ W2, const float* __restrict__ B2,
            const float* __restrict__ W3, const float* __restrict__ B3,
            float* __restrict__ out)
{
    extern __shared__ char smc[];
    const uint32_t sb = smem_u32(smc);
    const int t    = threadIdx.x;
    const int lane = t & 31;
    const int wrp  = t >> 5;
    const int qr   = lane >> 2;     // 0..7
    const int qc   = lane & 3;      // 0..3
    const int lm   = lane >> 3;     // ldmatrix sub-matrix id 0..3
    const int lr8  = lane & 7;      // ldmatrix row-within-matrix
    const int net  = blockIdx.y;    // network k = net+1
    const int k    = net + 1;
    const int brow0 = blockIdx.x * TPB;

    // ---- stage x tile -> bf16 hi/lo, swizzled 128B rows ----
    {
        const float4* gx = (const float4*)(x + (size_t)brow0 * 64);
        #pragma unroll
        for (int i = 0; i < 16; i++) {
            int idx = t + i * TPB;           // 0..2047 float4s
            int r = idx >> 4, q = idx & 15;
            float4 v = gx[idx];
            uint32_t h01, l01, h23, l23;
            split2p(v.x, v.y, h01, l01);
            split2p(v.z, v.w, h23, l23);
            int off = SW(r * 128 + q * 8);
            *(uint2*)(smc + SO_XH + off) = make_uint2(h01, h23);
            *(uint2*)(smc + SO_XL + off) = make_uint2(l01, l23);
        }
    }
    // ---- stage W1 (j>=k zeroed) and W2, NATIVE [j][n] layout, bf16 hi/lo ----
    {
        const float4* g1 = (const float4*)(W1 + (size_t)net * 4096);
        const float4* g2 = (const float4*)(W2 + (size_t)net * 4096);
        #pragma unroll
        for (int i = 0; i < 8; i++) {
            int i4 = t + i * TPB;            // 0..1023; (j, 4 n's)
            int j = i4 >> 4, n4 = i4 & 15;
            float4 v1 = g1[i4];
            float4 v2 = g2[i4];
            if (j >= k) { v1.x = v1.y = v1.z = v1.w = 0.0f; }  // causal mask
            int off = SW(j * 128 + n4 * 8);
            uint32_t h01, l01, h23, l23;
            split2p(v1.x, v1.y, h01, l01);
            split2p(v1.z, v1.w, h23, l23);
            *(uint2*)(smc + SO_W1H + off) = make_uint2(h01, h23);
            *(uint2*)(smc + SO_W1L + off) = make_uint2(l01, l23);
            split2p(v2.x, v2.y, h01, l01);
            split2p(v2.z, v2.w, h23, l23);
            *(uint2*)(smc + SO_W2H + off) = make_uint2(h01, h23);
            *(uint2*)(smc + SO_W2L + off) = make_uint2(l01, l23);
        }
        if (t < 64) {
            ((float*)(smc + SO_B1))[t] = B1[net * 64 + t];
            ((float*)(smc + SO_B2))[t] = B2[net * 64 + t];
            ((float2*)(smc + SO_W3))[t] =
                make_float2(W3[(size_t)net * 128 + 2 * t], W3[(size_t)net * 128 + 2 * t + 1]);
        }
        if (t == 0)
            *((float2*)(smc + SO_B3)) = make_float2(B3[net * 2], B3[net * 2 + 1]);
    }
    __syncthreads();

    const float* b1s = (const float*)(smc + SO_B1);
    const float* b2s = (const float*)(smc + SO_B2);
    const u64*   w3p = (const u64*)(smc + SO_W3);
    const float2 b3  = *(const float2*)(smc + SO_B3);
    const int kt1 = (k + 15) >> 4;     // causal trim of layer-1 k-tiles

    // ldmatrix address generators (per-lane)
    // A 16x16 tile at (rows mb*16+wrp*32, k-bytes kt*32): matrices m0..m3 in
    // a-frag register order.
    // B 16x16 region of W[j][n]: x4.trans gives (b0,b1) for n-tile p*2 and p*2+1.
    #define A_ADDR(base, mb, kt) \
        (sb + (base) + SW((wrp * 32 + (mb) * 16 + (lm & 1) * 8 + lr8) * 128 + (kt) * 32 + (lm >> 1) * 16))
    #define B_ADDR(base, kt, p) \
        (sb + (base) + SW(((kt) * 16 + (lm & 1) * 8 + lr8) * 128 + ((p) * 2 + (lm >> 1)) * 16))

    #pragma unroll 1
    for (int mb = 0; mb < 2; mb++) {
        // ============== layer 1: D1 = x[:, :k] @ W1m + B1 (3-pass) ==============
        float D1[8][4];
        #pragma unroll
        for (int n = 0; n < 8; n++) {
            float bx = b1s[n * 8 + qc * 2], by = b1s[n * 8 + qc * 2 + 1];
            D1[n][0] = bx; D1[n][1] = by; D1[n][2] = bx; D1[n][3] = by;
        }
        for (int kt = 0; kt < kt1; kt++) {
            uint32_t ah[4], al[4];
            ldsm_x4(ah, A_ADDR(SO_XH, mb, kt));
            ldsm_x4(al, A_ADDR(SO_XL, mb, kt));
            #pragma unroll
            for (int p = 0; p < 4; p++) {
                uint32_t bh[4], bl[4];
                ldsm_x4t(bh, B_ADDR(SO_W1H, kt, p));
                ldsm_x4t(bl, B_ADDR(SO_W1L, kt, p));
                mma16816(D1[2 * p],     ah, bh[0], bh[1]);
                mma16816(D1[2 * p],     al, bh[0], bh[1]);
                mma16816(D1[2 * p],     ah, bl[0], bl[1]);
                mma16816(D1[2 * p + 1], ah, bh[2], bh[3]);
                mma16816(D1[2 * p + 1], al, bh[2], bh[3]);
                mma16816(D1[2 * p + 1], ah, bl[2], bl[3]);
            }
        }

        // ============== layer 2: D2 = relu(D1) @ W2 + B2 (register-chained) =====
        float D2[8][4];
        #pragma unroll
        for (int n = 0; n < 8; n++) {
            float bx = b2s[n * 8 + qc * 2], by = b2s[n * 8 + qc * 2 + 1];
            D2[n][0] = bx; D2[n][1] = by; D2[n][2] = bx; D2[n][3] = by;
        }
        #pragma unroll
        for (int kt = 0; kt < 4; kt++) {
            // D-fragment of n-tiles {2kt, 2kt+1} == A-fragment of k-tile kt
            uint32_t ah[4], al[4];
            split2p(fmaxf(D1[2*kt  ][0], 0.f), fmaxf(D1[2*kt  ][1], 0.f), ah[0], al[0]);
            split2p(fmaxf(D1[2*kt  ][2], 0.f), fmaxf(D1[2*kt  ][3], 0.f), ah[1], al[1]);
            split2p(fmaxf(D1[2*kt+1][0], 0.f), fmaxf(D1[2*kt+1][1], 0.f), ah[2], al[2]);
            split2p(fmaxf(D1[2*kt+1][2], 0.f), fmaxf(D1[2*kt+1][3], 0.f), ah[3], al[3]);
            #pragma unroll
            for (int p = 0; p < 4; p++) {
                uint32_t bh[4], bl[4];
                ldsm_x4t(bh, B_ADDR(SO_W2H, kt, p));
                ldsm_x4t(bl, B_ADDR(SO_W2L, kt, p));
                mma16816(D2[2 * p],     ah, bh[0], bh[1]);
                mma16816(D2[2 * p],     al, bh[0], bh[1]);
                mma16816(D2[2 * p],     ah, bl[0], bl[1]);
                mma16816(D2[2 * p + 1], ah, bh[2], bh[3]);
                mma16816(D2[2 * p + 1], al, bh[2], bh[3]);
                mma16816(D2[2 * p + 1], ah, bl[2], bl[3]);
            }
        }

        // ============== layer 3: (scale, trans) = relu(D2) @ W3 + B3 ============
        {
            u64 po0 = 0ULL, po1 = 0ULL;    // rows qr, qr+8 of this m-block
            #pragma unroll
            for (int n = 0; n < 8; n++) {
                u64 wa = w3p[n * 8 + qc * 2];
                u64 wb = w3p[n * 8 + qc * 2 + 1];
                ffma2(po0, pack2(fmaxf(D2[n][0], 0.f)), wa);
                ffma2(po0, pack2(fmaxf(D2[n][1], 0.f)), wb);
                ffma2(po1, pack2(fmaxf(D2[n][2], 0.f)), wa);
                ffma2(po1, pack2(fmaxf(D2[n][3], 0.f)), wb);
            }
            #pragma unroll
            for (int h = 0; h < 2; h++) {
                float2 f = un2(h ? po1 : po0);
                f.x += __shfl_xor_sync(0xffffffffu, f.x, 1);
                f.y += __shfl_xor_sync(0xffffffffu, f.y, 1);
                f.x += __shfl_xor_sync(0xffffffffu, f.x, 2);
                f.y += __shfl_xor_sync(0xffffffffu, f.y, 2);
                if (qc == 0) {
                    int brow = brow0 + wrp * 32 + mb * 16 + h * 8 + qr;
                    out[(size_t)brow * 64 + k] = fminf(fmaxf(f.x + b3.x, -5.0f), 5.0f);
                    out[(size_t)(BATCHN + brow) * 64 + k] = f.y + b3.y;
                }
            }
        }
    }

    // ---- network 0: constant column (net==0 CTAs only) ----
    if (net == 0) {
        float s0 = c0[0], t0 = c0[1];
        #pragma unroll
        for (int h = 0; h < 64; h++) {
            float hv = fmaxf(w0[h] + b0[h], 0.0f);
            s0 = fmaf(hv, v0[2 * h],     s0);
            t0 = fmaf(hv, v0[2 * h + 1], t0);
        }
        const int brow = brow0 + t;
        out[(size_t)brow * 64] = fminf(fmaxf(s0, -5.0f), 5.0f);
        out[(size_t)(BATCHN + brow) * 64] = t0;
    }
}

extern "C" void kernel_launch(void* const* d_in, const int* in_sizes, int n_in,
                              void* d_out, int out_size)
{
    (void)in_sizes; (void)n_in; (void)out_size;
    const float* x  = (const float*)d_in[0];
    const float* w0 = (const float*)d_in[1];
    const float* b0 = (const float*)d_in[2];
    const float* v0 = (const float*)d_in[3];
    const float* c0 = (const float*)d_in[4];
    const float* W1 = (const float*)d_in[5];
    const float* B1 = (const float*)d_in[6];
    const float* W2 = (const float*)d_in[7];
    const float* B2 = (const float*)d_in[8];
    const float* W3 = (const float*)d_in[9];
    const float* B3 = (const float*)d_in[10];
    float* out = (float*)d_out;

    cudaFuncSetAttribute(arnet_hmma2,
                         cudaFuncAttributeMaxDynamicSharedMemorySize, SMEM_BYTES);

    dim3 grid(BATCHN / TPB, 63);   // (128, 63)
    arnet_hmma2<<<grid, TPB, SMEM_BYTES>>>(x, w0, b0, v0, c0,
                                           W1, B1, W2, B2, W3, B3, out);
}

// round 10
// speedup vs baseline: 2.1313x; 1.0772x over previous
#include <cuda_runtime.h>
#include <cuda_bf16.h>
#include <cstdint>

// AutoregressiveNetwork via HMMA mma.sync m16n8k16 bf16 + ldmatrix (sm_80 PTX;
// tcgen05 unavailable: harness emits compute_103, not 103a).
// 63 masked MLPs [B,k]->64->64->2, B=16384. CTA = (net, 128-row tile), 4 warps,
// each warp owns 32 rows. R10: single pass over all 32 rows (no m-block loop)
// so every A/B fragment is ldmatrix'd exactly once per warp (62 vs 114 LDSM);
// layer-3 folded into layer-2's n-pair loop so D2 never exceeds 16 live floats.
// 3-pass bf16 hi/lo split, fp32 accumulators.

#define BATCHN 16384
#define TPB    128

#define SO_XH  0         // x hi : 128 rows * 128B = 16384
#define SO_XL  16384
#define SO_W1H 32768     // W1 [j][n] bf16, 64 rows * 128B = 8192 (j>=k zeroed)
#define SO_W1L 40960
#define SO_W2H 49152
#define SO_W2L 57344
#define SO_W3  65536     // 64 x float2
#define SO_B1  66048     // 64 floats
#define SO_B2  66304
#define SO_B3  66560     // float2
#define SMEM_BYTES 66568

#define SW(o) ((o) ^ (((o) >> 3) & 0x70))   // SW128 swizzle (128B rows)

typedef unsigned long long u64;

static __device__ __forceinline__ uint32_t smem_u32(const void* p) {
    uint32_t a;
    asm("{ .reg .u64 t; cvta.to.shared.u64 t, %1; cvt.u32.u64 %0, t; }" : "=r"(a) : "l"(p));
    return a;
}
static __device__ __forceinline__ u64 pack2(float x) {
    u64 r; asm("mov.b64 %0, {%1, %1};" : "=l"(r) : "f"(x)); return r;
}
static __device__ __forceinline__ void ffma2(u64& d, u64 a, u64 b) {
    asm("fma.rn.f32x2 %0, %1, %2, %0;" : "+l"(d) : "l"(a), "l"(b));
}
static __device__ __forceinline__ float2 un2(u64 a) {
    float2 f; asm("mov.b64 {%0, %1}, %2;" : "=f"(f.x), "=f"(f.y) : "l"(a)); return f;
}
static __device__ __forceinline__ void split1(float v, __nv_bfloat16& h, __nv_bfloat16& l) {
    h = __float2bfloat16_rn(v);
    l = __float2bfloat16_rn(v - __bfloat162float(h));
}
static __device__ __forceinline__ void split2p(float a, float b, uint32_t& hp, uint32_t& lp) {
    __nv_bfloat16 ha, la, hb, lb;
    split1(a, ha, la); split1(b, hb, lb);
    hp = ((uint32_t)*(unsigned short*)&hb << 16) | *(unsigned short*)&ha;
    lp = ((uint32_t)*(unsigned short*)&lb << 16) | *(unsigned short*)&la;
}
static __device__ __forceinline__ void mma16816(float* d, const uint32_t* a,
                                                uint32_t b0, uint32_t b1) {
    asm volatile(
        "mma.sync.aligned.m16n8k16.row.col.f32.bf16.bf16.f32 "
        "{%0,%1,%2,%3}, {%4,%5,%6,%7}, {%8,%9}, {%0,%1,%2,%3};"
        : "+f"(d[0]), "+f"(d[1]), "+f"(d[2]), "+f"(d[3])
        : "r"(a[0]), "r"(a[1]), "r"(a[2]), "r"(a[3]), "r"(b0), "r"(b1));
}
static __device__ __forceinline__ void ldsm_x4(uint32_t* r, uint32_t addr) {
    asm volatile("ldmatrix.sync.aligned.m8n8.x4.shared.b16 {%0,%1,%2,%3}, [%4];"
        : "=r"(r[0]), "=r"(r[1]), "=r"(r[2]), "=r"(r[3]) : "r"(addr));
}
static __device__ __forceinline__ void ldsm_x4t(uint32_t* r, uint32_t addr) {
    asm volatile("ldmatrix.sync.aligned.m8n8.x4.trans.shared.b16 {%0,%1,%2,%3}, [%4];"
        : "=r"(r[0]), "=r"(r[1]), "=r"(r[2]), "=r"(r[3]) : "r"(addr));
}

__global__ void __launch_bounds__(TPB, 3)
arnet_hmma3(const float* __restrict__ x,
            const float* __restrict__ w0, const float* __restrict__ b0,
            const float* __restrict__ v0, const float* __restrict__ c0,
            const float* __restrict__ W1, const float* __restrict__ B1,
            const float* __restrict__ W2, const float* __restrict__ B2,
            const float* __restrict__ W3, const float* __restrict__ B3,
            float* __restrict__ out)
{
    extern __shared__ char smc[];
    const uint32_t sb = smem_u32(smc);
    const int t    = threadIdx.x;
    const int lane = t & 31;
    const int wrp  = t >> 5;
    const int qr   = lane >> 2;     // 0..7
    const int qc   = lane & 3;      // 0..3
    const int lm   = lane >> 3;     // ldmatrix sub-matrix id 0..3
    const int lr8  = lane & 7;      // ldmatrix row-within-matrix
    const int net  = blockIdx.y;    // network k = net+1
    const int k    = net + 1;
    const int brow0 = blockIdx.x * TPB;

    // ---- stage x tile -> bf16 hi/lo, swizzled 128B rows ----
    {
        const float4* gx = (const float4*)(x + (size_t)brow0 * 64);
        #pragma unroll
        for (int i = 0; i < 16; i++) {
            int idx = t + i * TPB;           // 0..2047 float4s
            int r = idx >> 4, q = idx & 15;
            float4 v = gx[idx];
            uint32_t h01, l01, h23, l23;
            split2p(v.x, v.y, h01, l01);
            split2p(v.z, v.w, h23, l23);
            int off = SW(r * 128 + q * 8);
            *(uint2*)(smc + SO_XH + off) = make_uint2(h01, h23);
            *(uint2*)(smc + SO_XL + off) = make_uint2(l01, l23);
        }
    }
    // ---- stage W1 (j>=k zeroed) and W2, NATIVE [j][n] layout, bf16 hi/lo ----
    {
        const float4* g1 = (const float4*)(W1 + (size_t)net * 4096);
        const float4* g2 = (const float4*)(W2 + (size_t)net * 4096);
        #pragma unroll
        for (int i = 0; i < 8; i++) {
            int i4 = t + i * TPB;            // 0..1023; (j, 4 n's)
            int j = i4 >> 4, n4 = i4 & 15;
            float4 v1 = g1[i4];
            float4 v2 = g2[i4];
            if (j >= k) { v1.x = v1.y = v1.z = v1.w = 0.0f; }  // causal mask
            int off = SW(j * 128 + n4 * 8);
            uint32_t h01, l01, h23, l23;
            split2p(v1.x, v1.y, h01, l01);
            split2p(v1.z, v1.w, h23, l23);
            *(uint2*)(smc + SO_W1H + off) = make_uint2(h01, h23);
            *(uint2*)(smc + SO_W1L + off) = make_uint2(l01, l23);
            split2p(v2.x, v2.y, h01, l01);
            split2p(v2.z, v2.w, h23, l23);
            *(uint2*)(smc + SO_W2H + off) = make_uint2(h01, h23);
            *(uint2*)(smc + SO_W2L + off) = make_uint2(l01, l23);
        }
        if (t < 64) {
            ((float*)(smc + SO_B1))[t] = B1[net * 64 + t];
            ((float*)(smc + SO_B2))[t] = B2[net * 64 + t];
            ((float2*)(smc + SO_W3))[t] =
                make_float2(W3[(size_t)net * 128 + 2 * t], W3[(size_t)net * 128 + 2 * t + 1]);
        }
        if (t == 0)
            *((float2*)(smc + SO_B3)) = make_float2(B3[net * 2], B3[net * 2 + 1]);
    }
    __syncthreads();

    const float* b1s = (const float*)(smc + SO_B1);
    const float* b2s = (const float*)(smc + SO_B2);
    const u64*   w3p = (const u64*)(smc + SO_W3);
    const float2 b3  = *(const float2*)(smc + SO_B3);
    const int kt1 = (k + 15) >> 4;     // causal trim of layer-1 k-tiles

    // ldmatrix per-lane address generators.
    // A: 16x16 tile at rows wrp*32 + m*16, k-bytes kt*32 (a-frag register order).
    // B: 16x16 region of W[j][n]; x4.trans yields (b0,b1)/(b2,b3) for n-tiles 2p, 2p+1.
    #define A_ADDR(base, m, kt) \
        (sb + (base) + SW((wrp * 32 + (m) * 16 + (lm & 1) * 8 + lr8) * 128 + (kt) * 32 + (lm >> 1) * 16))
    #define B_ADDR(base, kt, p) \
        (sb + (base) + SW(((kt) * 16 + (lm & 1) * 8 + lr8) * 128 + ((p) * 2 + (lm >> 1)) * 16))

    // ============== layer 1: D1 = x[:, :k] @ W1m + B1 (3-pass, 32 rows) ==========
    float D1[2][8][4];          // [m][n-tile][frag]
    #pragma unroll
    for (int n = 0; n < 8; n++) {
        float bx = b1s[n * 8 + qc * 2], by = b1s[n * 8 + qc * 2 + 1];
        #pragma unroll
        for (int m = 0; m < 2; m++) {
            D1[m][n][0] = bx; D1[m][n][1] = by; D1[m][n][2] = bx; D1[m][n][3] = by;
        }
    }
    for (int kt = 0; kt < kt1; kt++) {
        uint32_t ah[2][4], al[2][4];
        ldsm_x4(ah[0], A_ADDR(SO_XH, 0, kt));
        ldsm_x4(al[0], A_ADDR(SO_XL, 0, kt));
        ldsm_x4(ah[1], A_ADDR(SO_XH, 1, kt));
        ldsm_x4(al[1], A_ADDR(SO_XL, 1, kt));
        #pragma unroll
        for (int p = 0; p < 4; p++) {
            uint32_t bh[4], bl[4];
            ldsm_x4t(bh, B_ADDR(SO_W1H, kt, p));
            ldsm_x4t(bl, B_ADDR(SO_W1L, kt, p));
            #pragma unroll
            for (int m = 0; m < 2; m++) {
                mma16816(D1[m][2 * p],     ah[m], bh[0], bh[1]);
                mma16816(D1[m][2 * p],     al[m], bh[0], bh[1]);
                mma16816(D1[m][2 * p],     ah[m], bl[0], bl[1]);
                mma16816(D1[m][2 * p + 1], ah[m], bh[2], bh[3]);
                mma16816(D1[m][2 * p + 1], al[m], bh[2], bh[3]);
                mma16816(D1[m][2 * p + 1], ah[m], bl[2], bl[3]);
            }
        }
    }

    // ---- relu + split D1 -> persistent layer-2 A fragments (frees D1 in place) ----
    uint32_t a2h[4][2][4], a2l[4][2][4];   // [kt][m][frag]
    #pragma unroll
    for (int kt = 0; kt < 4; kt++) {
        #pragma unroll
        for (int m = 0; m < 2; m++) {
            split2p(fmaxf(D1[m][2*kt  ][0], 0.f), fmaxf(D1[m][2*kt  ][1], 0.f), a2h[kt][m][0], a2l[kt][m][0]);
            split2p(fmaxf(D1[m][2*kt  ][2], 0.f), fmaxf(D1[m][2*kt  ][3], 0.f), a2h[kt][m][1], a2l[kt][m][1]);
            split2p(fmaxf(D1[m][2*kt+1][0], 0.f), fmaxf(D1[m][2*kt+1][1], 0.f), a2h[kt][m][2], a2l[kt][m][2]);
            split2p(fmaxf(D1[m][2*kt+1][2], 0.f), fmaxf(D1[m][2*kt+1][3], 0.f), a2h[kt][m][3], a2l[kt][m][3]);
        }
    }

    // ====== layer 2 + streaming layer 3: per n-pair, finish k-reduction then fold ==
    u64 po[2][2] = {{0ULL, 0ULL}, {0ULL, 0ULL}};   // [m][row qr / qr+8] (out0,out1)
    #pragma unroll
    for (int p = 0; p < 4; p++) {
        float D2[2][2][4];       // [m][n-subtile][frag], only this n-pair live
        #pragma unroll
        for (int q = 0; q < 2; q++) {
            int n = 2 * p + q;
            float bx = b2s[n * 8 + qc * 2], by = b2s[n * 8 + qc * 2 + 1];
            #pragma unroll
            for (int m = 0; m < 2; m++) {
                D2[m][q][0] = bx; D2[m][q][1] = by; D2[m][q][2] = bx; D2[m][q][3] = by;
            }
        }
        #pragma unroll
        for (int kt = 0; kt < 4; kt++) {
            uint32_t bh[4], bl[4];
            ldsm_x4t(bh, B_ADDR(SO_W2H, kt, p));
            ldsm_x4t(bl, B_ADDR(SO_W2L, kt, p));
            #pragma unroll
            for (int m = 0; m < 2; m++) {
                mma16816(D2[m][0], a2h[kt][m], bh[0], bh[1]);
                mma16816(D2[m][0], a2l[kt][m], bh[0], bh[1]);
                mma16816(D2[m][0], a2h[kt][m], bl[0], bl[1]);
                mma16816(D2[m][1], a2h[kt][m], bh[2], bh[3]);
                mma16816(D2[m][1], a2l[kt][m], bh[2], bh[3]);
                mma16816(D2[m][1], a2h[kt][m], bl[2], bl[3]);
            }
        }
        // fold this n-pair into layer-3 partials, discard D2
        #pragma unroll
        for (int q = 0; q < 2; q++) {
            int n = 2 * p + q;
            u64 wa = w3p[n * 8 + qc * 2];
            u64 wb = w3p[n * 8 + qc * 2 + 1];
            #pragma unroll
            for (int m = 0; m < 2; m++) {
                ffma2(po[m][0], pack2(fmaxf(D2[m][q][0], 0.f)), wa);
                ffma2(po[m][0], pack2(fmaxf(D2[m][q][1], 0.f)), wb);
                ffma2(po[m][1], pack2(fmaxf(D2[m][q][2], 0.f)), wa);
                ffma2(po[m][1], pack2(fmaxf(D2[m][q][3], 0.f)), wb);
            }
        }
    }

    // ---- layer-3 cross-lane reduction + store ----
    #pragma unroll
    for (int m = 0; m < 2; m++) {
        #pragma unroll
        for (int h = 0; h < 2; h++) {
            float2 f = un2(po[m][h]);
            f.x += __shfl_xor_sync(0xffffffffu, f.x, 1);
            f.y += __shfl_xor_sync(0xffffffffu, f.y, 1);
            f.x += __shfl_xor_sync(0xffffffffu, f.x, 2);
            f.y += __shfl_xor_sync(0xffffffffu, f.y, 2);
            if (qc == 0) {
                int brow = brow0 + wrp * 32 + m * 16 + h * 8 + qr;
                out[(size_t)brow * 64 + k] = fminf(fmaxf(f.x + b3.x, -5.0f), 5.0f);
                out[(size_t)(BATCHN + brow) * 64 + k] = f.y + b3.y;
            }
        }
    }

    // ---- network 0: constant column (net==0 CTAs only) ----
    if (net == 0) {
        float s0 = c0[0], t0 = c0[1];
        #pragma unroll
        for (int h = 0; h < 64; h++) {
            float hv = fmaxf(w0[h] + b0[h], 0.0f);
            s0 = fmaf(hv, v0[2 * h],     s0);
            t0 = fmaf(hv, v0[2 * h + 1], t0);
        }
        const int brow = brow0 + t;
        out[(size_t)brow * 64] = fminf(fmaxf(s0, -5.0f), 5.0f);
        out[(size_t)(BATCHN + brow) * 64] = t0;
    }
}

extern "C" void kernel_launch(void* const* d_in, const int* in_sizes, int n_in,
                              void* d_out, int out_size)
{
    (void)in_sizes; (void)n_in; (void)out_size;
    const float* x  = (const float*)d_in[0];
    const float* w0 = (const float*)d_in[1];
    const float* b0 = (const float*)d_in[2];
    const float* v0 = (const float*)d_in[3];
    const float* c0 = (const float*)d_in[4];
    const float* W1 = (const float*)d_in[5];
    const float* B1 = (const float*)d_in[6];
    const float* W2 = (const float*)d_in[7];
    const float* B2 = (const float*)d_in[8];
    const float* W3 = (const float*)d_in[9];
    const float* B3 = (const float*)d_in[10];
    float* out = (float*)d_out;

    cudaFuncSetAttribute(arnet_hmma3,
                         cudaFuncAttributeMaxDynamicSharedMemorySize, SMEM_BYTES);

    dim3 grid(BATCHN / TPB, 63);   // (128, 63)
    arnet_hmma3<<<grid, TPB, SMEM_BYTES>>>(x, w0, b0, v0, c0,
                                           W1, B1, W2, B2, W3, B3, out);
}

// round 11
// speedup vs baseline: 3.6698x; 1.7218x over previous
#include <cuda_runtime.h>
#include <cuda_bf16.h>
#include <cstdint>

// AutoregressiveNetwork via HMMA mma.sync m16n8k16 bf16 + ldmatrix (sm_80 PTX;
// tcgen05 unavailable: harness emits compute_103, not 103a).
// 63 masked MLPs [B,k]->64->64->2, B=16384. CTA = (net, 128-row tile), 4 warps.
// R11: two prep kernels precompute swizzled bf16 hi/lo SMEM images of x and of
// the (causally masked) weights in __device__ scratch, so main-kernel staging
// is 32 verbatim float4 copies per thread (R10 spent ~60% of its issue slots
// re-splitting the same data in every CTA). Mainloop identical to R10.

#define BATCHN 16384
#define TPB    128

#define SO_XH  0         // x hi : 128 rows * 128B = 16384
#define SO_XL  16384
#define SO_W1H 32768     // W1 [j][n] bf16, 64 rows * 128B = 8192 (j>=k zeroed)
#define SO_W1L 40960
#define SO_W2H 49152
#define SO_W2L 57344
#define SO_W3  65536     // 64 x float2
#define SO_B1  66048     // 64 floats
#define SO_B2  66304
#define SO_B3  66560     // float2
#define SMEM_BYTES 66568

#define SW(o) ((o) ^ (((o) >> 3) & 0x70))   // SW128 swizzle (128B rows)

typedef unsigned long long u64;

// ---- precomputed swizzled images (device scratch; static alloc is allowed) ----
__device__ __align__(16) char gXH[128 * 16384];   // per 128-row tile: 16KB hi
__device__ __align__(16) char gXL[128 * 16384];   //                        lo
__device__ __align__(16) char gW1H[63 * 8192];    // per net: 8KB, causal-masked
__device__ __align__(16) char gW1L[63 * 8192];
__device__ __align__(16) char gW2H[63 * 8192];
__device__ __align__(16) char gW2L[63 * 8192];

static __device__ __forceinline__ uint32_t smem_u32(const void* p) {
    uint32_t a;
    asm("{ .reg .u64 t; cvta.to.shared.u64 t, %1; cvt.u32.u64 %0, t; }" : "=r"(a) : "l"(p));
    return a;
}
static __device__ __forceinline__ u64 pack2(float x) {
    u64 r; asm("mov.b64 %0, {%1, %1};" : "=l"(r) : "f"(x)); return r;
}
static __device__ __forceinline__ void ffma2(u64& d, u64 a, u64 b) {
    asm("fma.rn.f32x2 %0, %1, %2, %0;" : "+l"(d) : "l"(a), "l"(b));
}
static __device__ __forceinline__ float2 un2(u64 a) {
    float2 f; asm("mov.b64 {%0, %1}, %2;" : "=f"(f.x), "=f"(f.y) : "l"(a)); return f;
}
static __device__ __forceinline__ void split1(float v, __nv_bfloat16& h, __nv_bfloat16& l) {
    h = __float2bfloat16_rn(v);
    l = __float2bfloat16_rn(v - __bfloat162float(h));
}
static __device__ __forceinline__ void split2p(float a, float b, uint32_t& hp, uint32_t& lp) {
    __nv_bfloat16 ha, la, hb, lb;
    split1(a, ha, la); split1(b, hb, lb);
    hp = ((uint32_t)*(unsigned short*)&hb << 16) | *(unsigned short*)&ha;
    lp = ((uint32_t)*(unsigned short*)&lb << 16) | *(unsigned short*)&la;
}
static __device__ __forceinline__ void mma16816(float* d, const uint32_t* a,
                                                uint32_t b0, uint32_t b1) {
    asm volatile(
        "mma.sync.aligned.m16n8k16.row.col.f32.bf16.bf16.f32 "
        "{%0,%1,%2,%3}, {%4,%5,%6,%7}, {%8,%9}, {%0,%1,%2,%3};"
        : "+f"(d[0]), "+f"(d[1]), "+f"(d[2]), "+f"(d[3])
        : "r"(a[0]), "r"(a[1]), "r"(a[2]), "r"(a[3]), "r"(b0), "r"(b1));
}
static __device__ __forceinline__ void ldsm_x4(uint32_t* r, uint32_t addr) {
    asm volatile("ldmatrix.sync.aligned.m8n8.x4.shared.b16 {%0,%1,%2,%3}, [%4];"
        : "=r"(r[0]), "=r"(r[1]), "=r"(r[2]), "=r"(r[3]) : "r"(addr));
}
static __device__ __forceinline__ void ldsm_x4t(uint32_t* r, uint32_t addr) {
    asm volatile("ldmatrix.sync.aligned.m8n8.x4.trans.shared.b16 {%0,%1,%2,%3}, [%4];"
        : "=r"(r[0]), "=r"(r[1]), "=r"(r[2]), "=r"(r[3]) : "r"(addr));
}

// ============ prep kernel 1: x -> swizzled bf16 hi/lo tile images ============
__global__ void __launch_bounds__(TPB)
prep_x(const float* __restrict__ x)
{
    const int tt = blockIdx.x;          // tile 0..127 (128 rows each)
    const int t  = threadIdx.x;
    const float4* gx = (const float4*)(x + (size_t)tt * 128 * 64);
    char* dh = gXH + (size_t)tt * 16384;
    char* dl = gXL + (size_t)tt * 16384;
    #pragma unroll
    for (int i = 0; i < 16; i++) {
        int idx = t + i * TPB;           // 0..2047 float4s
        int r = idx >> 4, q = idx & 15;
        float4 v = gx[idx];
        uint32_t h01, l01, h23, l23;
        split2p(v.x, v.y, h01, l01);
        split2p(v.z, v.w, h23, l23);
        int off = SW(r * 128 + q * 8);
        *(uint2*)(dh + off) = make_uint2(h01, h23);
        *(uint2*)(dl + off) = make_uint2(l01, l23);
    }
}

// ====== prep kernel 2: W1 (causal-masked) / W2 -> swizzled hi/lo images ======
__global__ void __launch_bounds__(TPB)
prep_w(const float* __restrict__ W1, const float* __restrict__ W2)
{
    const int net = blockIdx.x;          // 0..62, k = net+1
    const int k   = net + 1;
    const int t   = threadIdx.x;
    const float4* g1 = (const float4*)(W1 + (size_t)net * 4096);
    const float4* g2 = (const float4*)(W2 + (size_t)net * 4096);
    char* d1h = gW1H + (size_t)net * 8192;
    char* d1l = gW1L + (size_t)net * 8192;
    char* d2h = gW2H + (size_t)net * 8192;
    char* d2l = gW2L + (size_t)net * 8192;
    #pragma unroll
    for (int i = 0; i < 8; i++) {
        int i4 = t + i * TPB;            // 0..1023; (j, 4 n's)
        int j = i4 >> 4, n4 = i4 & 15;
        float4 v1 = g1[i4];
        float4 v2 = g2[i4];
        if (j >= k) { v1.x = v1.y = v1.z = v1.w = 0.0f; }   // causal mask
        int off = SW(j * 128 + n4 * 8);
        uint32_t h01, l01, h23, l23;
        split2p(v1.x, v1.y, h01, l01);
        split2p(v1.z, v1.w, h23, l23);
        *(uint2*)(d1h + off) = make_uint2(h01, h23);
        *(uint2*)(d1l + off) = make_uint2(l01, l23);
        split2p(v2.x, v2.y, h01, l01);
        split2p(v2.z, v2.w, h23, l23);
        *(uint2*)(d2h + off) = make_uint2(h01, h23);
        *(uint2*)(d2l + off) = make_uint2(l01, l23);
    }
}

// ============================== main kernel ==================================
__global__ void __launch_bounds__(TPB, 3)
arnet_hmma4(const float* __restrict__ w0, const float* __restrict__ b0,
            const float* __restrict__ v0, const float* __restrict__ c0,
            const float* __restrict__ B1, const float* __restrict__ B2,
            const float* __restrict__ W3, const float* __restrict__ B3,
            float* __restrict__ out)
{
    extern __shared__ char smc[];
    const uint32_t sb = smem_u32(smc);
    const int t    = threadIdx.x;
    const int lane = t & 31;
    const int wrp  = t >> 5;
    const int qr   = lane >> 2;     // 0..7
    const int qc   = lane & 3;      // 0..3
    const int lm   = lane >> 3;     // ldmatrix sub-matrix id 0..3
    const int lr8  = lane & 7;      // ldmatrix row-within-matrix
    const int net  = blockIdx.y;    // network k = net+1
    const int k    = net + 1;
    const int brow0 = blockIdx.x * TPB;

    // ---- staging = verbatim float4 copies of precomputed swizzled images ----
    {
        const float4* sxh = (const float4*)(gXH + (size_t)blockIdx.x * 16384);
        const float4* sxl = (const float4*)(gXL + (size_t)blockIdx.x * 16384);
        float4* dxh = (float4*)(smc + SO_XH);
        float4* dxl = (float4*)(smc + SO_XL);
        #pragma unroll
        for (int i = 0; i < 8; i++) {
            dxh[t + i * TPB] = sxh[t + i * TPB];
            dxl[t + i * TPB] = sxl[t + i * TPB];
        }
        const float4* s1h = (const float4*)(gW1H + (size_t)net * 8192);
        const float4* s1l = (const float4*)(gW1L + (size_t)net * 8192);
        const float4* s2h = (const float4*)(gW2H + (size_t)net * 8192);
        const float4* s2l = (const float4*)(gW2L + (size_t)net * 8192);
        float4* d1h = (float4*)(smc + SO_W1H);
        float4* d1l = (float4*)(smc + SO_W1L);
        float4* d2h = (float4*)(smc + SO_W2H);
        float4* d2l = (float4*)(smc + SO_W2L);
        #pragma unroll
        for (int i = 0; i < 4; i++) {
            d1h[t + i * TPB] = s1h[t + i * TPB];
            d1l[t + i * TPB] = s1l[t + i * TPB];
            d2h[t + i * TPB] = s2h[t + i * TPB];
            d2l[t + i * TPB] = s2l[t + i * TPB];
        }
        if (t < 64) {
            ((float*)(smc + SO_B1))[t] = B1[net * 64 + t];
            ((float*)(smc + SO_B2))[t] = B2[net * 64 + t];
            ((float2*)(smc + SO_W3))[t] =
                make_float2(W3[(size_t)net * 128 + 2 * t], W3[(size_t)net * 128 + 2 * t + 1]);
        }
        if (t == 0)
            *((float2*)(smc + SO_B3)) = make_float2(B3[net * 2], B3[net * 2 + 1]);
    }
    __syncthreads();

    const float* b1s = (const float*)(smc + SO_B1);
    const float* b2s = (const float*)(smc + SO_B2);
    const u64*   w3p = (const u64*)(smc + SO_W3);
    const float2 b3  = *(const float2*)(smc + SO_B3);
    const int kt1 = (k + 15) >> 4;     // causal trim of layer-1 k-tiles

    #define A_ADDR(base, m, kt) \
        (sb + (base) + SW((wrp * 32 + (m) * 16 + (lm & 1) * 8 + lr8) * 128 + (kt) * 32 + (lm >> 1) * 16))
    #define B_ADDR(base, kt, p) \
        (sb + (base) + SW(((kt) * 16 + (lm & 1) * 8 + lr8) * 128 + ((p) * 2 + (lm >> 1)) * 16))

    // ============== layer 1: D1 = x[:, :k] @ W1m + B1 (3-pass, 32 rows) ==========
    float D1[2][8][4];          // [m][n-tile][frag]
    #pragma unroll
    for (int n = 0; n < 8; n++) {
        float bx = b1s[n * 8 + qc * 2], by = b1s[n * 8 + qc * 2 + 1];
        #pragma unroll
        for (int m = 0; m < 2; m++) {
            D1[m][n][0] = bx; D1[m][n][1] = by; D1[m][n][2] = bx; D1[m][n][3] = by;
        }
    }
    for (int kt = 0; kt < kt1; kt++) {
        uint32_t ah[2][4], al[2][4];
        ldsm_x4(ah[0], A_ADDR(SO_XH, 0, kt));
        ldsm_x4(al[0], A_ADDR(SO_XL, 0, kt));
        ldsm_x4(ah[1], A_ADDR(SO_XH, 1, kt));
        ldsm_x4(al[1], A_ADDR(SO_XL, 1, kt));
        #pragma unroll
        for (int p = 0; p < 4; p++) {
            uint32_t bh[4], bl[4];
            ldsm_x4t(bh, B_ADDR(SO_W1H, kt, p));
            ldsm_x4t(bl, B_ADDR(SO_W1L, kt, p));
            #pragma unroll
            for (int m = 0; m < 2; m++) {
                mma16816(D1[m][2 * p],     ah[m], bh[0], bh[1]);
                mma16816(D1[m][2 * p],     al[m], bh[0], bh[1]);
                mma16816(D1[m][2 * p],     ah[m], bl[0], bl[1]);
                mma16816(D1[m][2 * p + 1], ah[m], bh[2], bh[3]);
                mma16816(D1[m][2 * p + 1], al[m], bh[2], bh[3]);
                mma16816(D1[m][2 * p + 1], ah[m], bl[2], bl[3]);
            }
        }
    }

    // ---- relu + split D1 -> persistent layer-2 A fragments ----
    uint32_t a2h[4][2][4], a2l[4][2][4];   // [kt][m][frag]
    #pragma unroll
    for (int kt = 0; kt < 4; kt++) {
        #pragma unroll
        for (int m = 0; m < 2; m++) {
            split2p(fmaxf(D1[m][2*kt  ][0], 0.f), fmaxf(D1[m][2*kt  ][1], 0.f), a2h[kt][m][0], a2l[kt][m][0]);
            split2p(fmaxf(D1[m][2*kt  ][2], 0.f), fmaxf(D1[m][2*kt  ][3], 0.f), a2h[kt][m][1], a2l[kt][m][1]);
            split2p(fmaxf(D1[m][2*kt+1][0], 0.f), fmaxf(D1[m][2*kt+1][1], 0.f), a2h[kt][m][2], a2l[kt][m][2]);
            split2p(fmaxf(D1[m][2*kt+1][2], 0.f), fmaxf(D1[m][2*kt+1][3], 0.f), a2h[kt][m][3], a2l[kt][m][3]);
        }
    }

    // ====== layer 2 + streaming layer 3: per n-pair, finish k-reduction then fold ==
    u64 po[2][2] = {{0ULL, 0ULL}, {0ULL, 0ULL}};   // [m][row qr / qr+8] (out0,out1)
    #pragma unroll
    for (int p = 0; p < 4; p++) {
        float D2[2][2][4];       // [m][n-subtile][frag], only this n-pair live
        #pragma unroll
        for (int q = 0; q < 2; q++) {
            int n = 2 * p + q;
            float bx = b2s[n * 8 + qc * 2], by = b2s[n * 8 + qc * 2 + 1];
            #pragma unroll
            for (int m = 0; m < 2; m++) {
                D2[m][q][0] = bx; D2[m][q][1] = by; D2[m][q][2] = bx; D2[m][q][3] = by;
            }
        }
        #pragma unroll
        for (int kt = 0; kt < 4; kt++) {
            uint32_t bh[4], bl[4];
            ldsm_x4t(bh, B_ADDR(SO_W2H, kt, p));
            ldsm_x4t(bl, B_ADDR(SO_W2L, kt, p));
            #pragma unroll
            for (int m = 0; m < 2; m++) {
                mma16816(D2[m][0], a2h[kt][m], bh[0], bh[1]);
                mma16816(D2[m][0], a2l[kt][m], bh[0], bh[1]);
                mma16816(D2[m][0], a2h[kt][m], bl[0], bl[1]);
                mma16816(D2[m][1], a2h[kt][m], bh[2], bh[3]);
                mma16816(D2[m][1], a2l[kt][m], bh[2], bh[3]);
                mma16816(D2[m][1], a2h[kt][m], bl[2], bl[3]);
            }
        }
        #pragma unroll
        for (int q = 0; q < 2; q++) {
            int n = 2 * p + q;
            u64 wa = w3p[n * 8 + qc * 2];
            u64 wb = w3p[n * 8 + qc * 2 + 1];
            #pragma unroll
            for (int m = 0; m < 2; m++) {
                ffma2(po[m][0], pack2(fmaxf(D2[m][q][0], 0.f)), wa);
                ffma2(po[m][0], pack2(fmaxf(D2[m][q][1], 0.f)), wb);
                ffma2(po[m][1], pack2(fmaxf(D2[m][q][2], 0.f)), wa);
                ffma2(po[m][1], pack2(fmaxf(D2[m][q][3], 0.f)), wb);
            }
        }
    }

    // ---- layer-3 cross-lane reduction + store ----
    #pragma unroll
    for (int m = 0; m < 2; m++) {
        #pragma unroll
        for (int h = 0; h < 2; h++) {
            float2 f = un2(po[m][h]);
            f.x += __shfl_xor_sync(0xffffffffu, f.x, 1);
            f.y += __shfl_xor_sync(0xffffffffu, f.y, 1);
            f.x += __shfl_xor_sync(0xffffffffu, f.x, 2);
            f.y += __shfl_xor_sync(0xffffffffu, f.y, 2);
            if (qc == 0) {
                int brow = brow0 + wrp * 32 + m * 16 + h * 8 + qr;
                out[(size_t)brow * 64 + k] = fminf(fmaxf(f.x + b3.x, -5.0f), 5.0f);
                out[(size_t)(BATCHN + brow) * 64 + k] = f.y + b3.y;
            }
        }
    }

    // ---- network 0: constant column (net==0 CTAs only) ----
    if (net == 0) {
        float s0 = c0[0], t0 = c0[1];
        #pragma unroll
        for (int h = 0; h < 64; h++) {
            float hv = fmaxf(w0[h] + b0[h], 0.0f);
            s0 = fmaf(hv, v0[2 * h],     s0);
            t0 = fmaf(hv, v0[2 * h + 1], t0);
        }
        const int brow = brow0 + t;
        out[(size_t)brow * 64] = fminf(fmaxf(s0, -5.0f), 5.0f);
        out[(size_t)(BATCHN + brow) * 64] = t0;
    }
}

extern "C" void kernel_launch(void* const* d_in, const int* in_sizes, int n_in,
                              void* d_out, int out_size)
{
    (void)in_sizes; (void)n_in; (void)out_size;
    const float* x  = (const float*)d_in[0];
    const float* w0 = (const float*)d_in[1];
    const float* b0 = (const float*)d_in[2];
    const float* v0 = (const float*)d_in[3];
    const float* c0 = (const float*)d_in[4];
    const float* W1 = (const float*)d_in[5];
    const float* B1 = (const float*)d_in[6];
    const float* W2 = (const float*)d_in[7];
    const float* B2 = (const float*)d_in[8];
    const float* W3 = (const float*)d_in[9];
    const float* B3 = (const float*)d_in[10];
    float* out = (float*)d_out;

    cudaFuncSetAttribute(arnet_hmma4,
                         cudaFuncAttributeMaxDynamicSharedMemorySize, SMEM_BYTES);

    prep_x<<<128, TPB>>>(x);
    prep_w<<<63, TPB>>>(W1, W2);
    dim3 grid(BATCHN / TPB, 63);   // (128, 63)
    arnet_hmma4<<<grid, TPB, SMEM_BYTES>>>(w0, b0, v0, c0,
                                           B1, B2, W3, B3, out);
}

// round 12
// speedup vs baseline: 4.7645x; 1.2983x over previous
#include <cuda_runtime.h>
#include <cuda_fp16.h>
#include <cstdint>

// AutoregressiveNetwork via HMMA mma.sync m16n8k16 fp16 + ldmatrix (sm_80 PTX;
// tcgen05 unavailable: harness emits compute_103, not 103a).
// 63 masked MLPs [B,k]->64->64->2, B=16384. CTA = (net, 128-row tile), 4 warps.
// R12: fp16 2-pass split (weights = wh + wl, activations single fp16) replaces
// bf16 3-pass: 33% fewer MMAs (R11 was tensor-pipe-bound ~95%), no A-lo buffer
// -> SMEM 49KB -> 4 CTAs/SM. Per-layer rel err ~2^-12 (~2.4e-4), under 1e-3.
// Prep kernels precompute swizzled fp16 images (amortized across 8064 CTAs).

#define BATCHN 16384
#define TPB    128

#define SO_XH  0         // x fp16 : 128 rows * 128B = 16384
#define SO_W1H 16384     // W1 [j][n] fp16 hi, 64 rows * 128B = 8192 (j>=k zeroed)
#define SO_W1L 24576
#define SO_W2H 32768
#define SO_W2L 40960
#define SO_W3  49152     // 64 x float2
#define SO_B1  49664     // 64 floats
#define SO_B2  49920
#define SO_B3  50176     // float2
#define SMEM_BYTES 50184

#define SW(o) ((o) ^ (((o) >> 3) & 0x70))   // SW128 swizzle (128B rows)

typedef unsigned long long u64;

// ---- precomputed swizzled fp16 images (device scratch) ----
__device__ __align__(16) char gXH[128 * 16384];   // per 128-row tile: 16KB
__device__ __align__(16) char gW1H[63 * 8192];    // per net, causal-masked
__device__ __align__(16) char gW1L[63 * 8192];
__device__ __align__(16) char gW2H[63 * 8192];
__device__ __align__(16) char gW2L[63 * 8192];

static __device__ __forceinline__ uint32_t smem_u32(const void* p) {
    uint32_t a;
    asm("{ .reg .u64 t; cvta.to.shared.u64 t, %1; cvt.u32.u64 %0, t; }" : "=r"(a) : "l"(p));
    return a;
}
static __device__ __forceinline__ u64 pack2(float x) {
    u64 r; asm("mov.b64 %0, {%1, %1};" : "=l"(r) : "f"(x)); return r;
}
static __device__ __forceinline__ void ffma2(u64& d, u64 a, u64 b) {
    asm("fma.rn.f32x2 %0, %1, %2, %0;" : "+l"(d) : "l"(a), "l"(b));
}
static __device__ __forceinline__ float2 un2(u64 a) {
    float2 f; asm("mov.b64 {%0, %1}, %2;" : "=f"(f.x), "=f"(f.y) : "l"(a)); return f;
}
// pack two floats as fp16x2 (a -> low half)
static __device__ __forceinline__ uint32_t h2pack(float a, float b) {
    __half2 h = __floats2half2_rn(a, b);
    return *(uint32_t*)&h;
}
// fp16 hi/lo split of a float pair
static __device__ __forceinline__ void hsplit2p(float a, float b, uint32_t& hp, uint32_t& lp) {
    __half ha = __float2half_rn(a), hb = __float2half_rn(b);
    float ra = a - __half2float(ha), rb = b - __half2float(hb);
    __half la = __float2half_rn(ra), lb = __float2half_rn(rb);
    hp = ((uint32_t)*(unsigned short*)&hb << 16) | *(unsigned short*)&ha;
    lp = ((uint32_t)*(unsigned short*)&lb << 16) | *(unsigned short*)&la;
}
static __device__ __forceinline__ void mma16816(float* d, const uint32_t* a,
                                                uint32_t b0, uint32_t b1) {
    asm volatile(
        "mma.sync.aligned.m16n8k16.row.col.f32.f16.f16.f32 "
        "{%0,%1,%2,%3}, {%4,%5,%6,%7}, {%8,%9}, {%0,%1,%2,%3};"
        : "+f"(d[0]), "+f"(d[1]), "+f"(d[2]), "+f"(d[3])
        : "r"(a[0]), "r"(a[1]), "r"(a[2]), "r"(a[3]), "r"(b0), "r"(b1));
}
static __device__ __forceinline__ void ldsm_x4(uint32_t* r, uint32_t addr) {
    asm volatile("ldmatrix.sync.aligned.m8n8.x4.shared.b16 {%0,%1,%2,%3}, [%4];"
        : "=r"(r[0]), "=r"(r[1]), "=r"(r[2]), "=r"(r[3]) : "r"(addr));
}
static __device__ __forceinline__ void ldsm_x4t(uint32_t* r, uint32_t addr) {
    asm volatile("ldmatrix.sync.aligned.m8n8.x4.trans.shared.b16 {%0,%1,%2,%3}, [%4];"
        : "=r"(r[0]), "=r"(r[1]), "=r"(r[2]), "=r"(r[3]) : "r"(addr));
}

// ============ prep kernel 1: x -> swizzled fp16 tile images ============
__global__ void __launch_bounds__(TPB)
prep_x(const float* __restrict__ x)
{
    const int tt   = blockIdx.x >> 1;        // tile 0..127
    const int half = blockIdx.x & 1;         // half-tile
    const int t    = threadIdx.x;
    const float4* gx = (const float4*)(x + (size_t)tt * 128 * 64);
    char* dh = gXH + (size_t)tt * 16384;
    #pragma unroll
    for (int i = 0; i < 8; i++) {
        int idx = half * 1024 + t + i * TPB;   // 0..2047 float4s
        int r = idx >> 4, q = idx & 15;
        float4 v = gx[idx];
        __half2 p0 = __floats2half2_rn(v.x, v.y);
        __half2 p1 = __floats2half2_rn(v.z, v.w);
        int off = SW(r * 128 + q * 8);
        *(uint2*)(dh + off) = make_uint2(*(uint32_t*)&p0, *(uint32_t*)&p1);
    }
}

// ====== prep kernel 2: W1 (causal-masked) / W2 -> swizzled fp16 hi/lo ======
__global__ void __launch_bounds__(TPB)
prep_w(const float* __restrict__ W1, const float* __restrict__ W2)
{
    const int net = blockIdx.x;          // 0..62, k = net+1
    const int k   = net + 1;
    const int t   = threadIdx.x;
    const float4* g1 = (const float4*)(W1 + (size_t)net * 4096);
    const float4* g2 = (const float4*)(W2 + (size_t)net * 4096);
    char* d1h = gW1H + (size_t)net * 8192;
    char* d1l = gW1L + (size_t)net * 8192;
    char* d2h = gW2H + (size_t)net * 8192;
    char* d2l = gW2L + (size_t)net * 8192;
    #pragma unroll
    for (int i = 0; i < 8; i++) {
        int i4 = t + i * TPB;            // 0..1023; (j, 4 n's)
        int j = i4 >> 4, n4 = i4 & 15;
        float4 v1 = g1[i4];
        float4 v2 = g2[i4];
        if (j >= k) { v1.x = v1.y = v1.z = v1.w = 0.0f; }   // causal mask
        int off = SW(j * 128 + n4 * 8);
        uint32_t h01, l01, h23, l23;
        hsplit2p(v1.x, v1.y, h01, l01);
        hsplit2p(v1.z, v1.w, h23, l23);
        *(uint2*)(d1h + off) = make_uint2(h01, h23);
        *(uint2*)(d1l + off) = make_uint2(l01, l23);
        hsplit2p(v2.x, v2.y, h01, l01);
        hsplit2p(v2.z, v2.w, h23, l23);
        *(uint2*)(d2h + off) = make_uint2(h01, h23);
        *(uint2*)(d2l + off) = make_uint2(l01, l23);
    }
}

// ============================== main kernel ==================================
__global__ void __launch_bounds__(TPB, 4)
arnet_hmma5(const float* __restrict__ w0, const float* __restrict__ b0,
            const float* __restrict__ v0, const float* __restrict__ c0,
            const float* __restrict__ B1, const float* __restrict__ B2,
            const float* __restrict__ W3, const float* __restrict__ B3,
            float* __restrict__ out)
{
    extern __shared__ char smc[];
    const uint32_t sb = smem_u32(smc);
    const int t    = threadIdx.x;
    const int lane = t & 31;
    const int wrp  = t >> 5;
    const int qr   = lane >> 2;     // 0..7
    const int qc   = lane & 3;      // 0..3
    const int lm   = lane >> 3;     // ldmatrix sub-matrix id 0..3
    const int lr8  = lane & 7;      // ldmatrix row-within-matrix
    const int net  = blockIdx.y;    // network k = net+1
    const int k    = net + 1;
    const int brow0 = blockIdx.x * TPB;

    // ---- staging = verbatim float4 copies of precomputed images ----
    {
        const float4* sxh = (const float4*)(gXH + (size_t)blockIdx.x * 16384);
        float4* dxh = (float4*)(smc + SO_XH);
        #pragma unroll
        for (int i = 0; i < 8; i++)
            dxh[t + i * TPB] = sxh[t + i * TPB];
        const float4* s1h = (const float4*)(gW1H + (size_t)net * 8192);
        const float4* s1l = (const float4*)(gW1L + (size_t)net * 8192);
        const float4* s2h = (const float4*)(gW2H + (size_t)net * 8192);
        const float4* s2l = (const float4*)(gW2L + (size_t)net * 8192);
        float4* d1h = (float4*)(smc + SO_W1H);
        float4* d1l = (float4*)(smc + SO_W1L);
        float4* d2h = (float4*)(smc + SO_W2H);
        float4* d2l = (float4*)(smc + SO_W2L);
        #pragma unroll
        for (int i = 0; i < 4; i++) {
            d1h[t + i * TPB] = s1h[t + i * TPB];
            d1l[t + i * TPB] = s1l[t + i * TPB];
            d2h[t + i * TPB] = s2h[t + i * TPB];
            d2l[t + i * TPB] = s2l[t + i * TPB];
        }
        if (t < 64) {
            ((float*)(smc + SO_B1))[t] = B1[net * 64 + t];
            ((float*)(smc + SO_B2))[t] = B2[net * 64 + t];
            ((float2*)(smc + SO_W3))[t] =
                make_float2(W3[(size_t)net * 128 + 2 * t], W3[(size_t)net * 128 + 2 * t + 1]);
        }
        if (t == 0)
            *((float2*)(smc + SO_B3)) = make_float2(B3[net * 2], B3[net * 2 + 1]);
    }
    __syncthreads();

    const float* b1s = (const float*)(smc + SO_B1);
    const float* b2s = (const float*)(smc + SO_B2);
    const u64*   w3p = (const u64*)(smc + SO_W3);
    const float2 b3  = *(const float2*)(smc + SO_B3);
    const int kt1 = (k + 15) >> 4;     // causal trim of layer-1 k-tiles

    #define A_ADDR(base, m, kt) \
        (sb + (base) + SW((wrp * 32 + (m) * 16 + (lm & 1) * 8 + lr8) * 128 + (kt) * 32 + (lm >> 1) * 16))
    #define B_ADDR(base, kt, p) \
        (sb + (base) + SW(((kt) * 16 + (lm & 1) * 8 + lr8) * 128 + ((p) * 2 + (lm >> 1)) * 16))

    // ====== layer 1: D1 = x[:, :k] @ (W1h + W1l) + B1  (2-pass, 32 rows) =======
    float D1[2][8][4];          // [m][n-tile][frag]
    #pragma unroll
    for (int n = 0; n < 8; n++) {
        float bx = b1s[n * 8 + qc * 2], by = b1s[n * 8 + qc * 2 + 1];
        #pragma unroll
        for (int m = 0; m < 2; m++) {
            D1[m][n][0] = bx; D1[m][n][1] = by; D1[m][n][2] = bx; D1[m][n][3] = by;
        }
    }
    for (int kt = 0; kt < kt1; kt++) {
        uint32_t a[2][4];
        ldsm_x4(a[0], A_ADDR(SO_XH, 0, kt));
        ldsm_x4(a[1], A_ADDR(SO_XH, 1, kt));
        #pragma unroll
        for (int p = 0; p < 4; p++) {
            uint32_t bh[4], bl[4];
            ldsm_x4t(bh, B_ADDR(SO_W1H, kt, p));
            ldsm_x4t(bl, B_ADDR(SO_W1L, kt, p));
            #pragma unroll
            for (int m = 0; m < 2; m++) {
                mma16816(D1[m][2 * p],     a[m], bh[0], bh[1]);
                mma16816(D1[m][2 * p],     a[m], bl[0], bl[1]);
                mma16816(D1[m][2 * p + 1], a[m], bh[2], bh[3]);
                mma16816(D1[m][2 * p + 1], a[m], bl[2], bl[3]);
            }
        }
    }

    // ---- relu + fp16-round D1 -> persistent layer-2 A fragments ----
    uint32_t a2[4][2][4];       // [kt][m][frag]
    #pragma unroll
    for (int kt = 0; kt < 4; kt++) {
        #pragma unroll
        for (int m = 0; m < 2; m++) {
            a2[kt][m][0] = h2pack(fmaxf(D1[m][2*kt  ][0], 0.f), fmaxf(D1[m][2*kt  ][1], 0.f));
            a2[kt][m][1] = h2pack(fmaxf(D1[m][2*kt  ][2], 0.f), fmaxf(D1[m][2*kt  ][3], 0.f));
            a2[kt][m][2] = h2pack(fmaxf(D1[m][2*kt+1][0], 0.f), fmaxf(D1[m][2*kt+1][1], 0.f));
            a2[kt][m][3] = h2pack(fmaxf(D1[m][2*kt+1][2], 0.f), fmaxf(D1[m][2*kt+1][3], 0.f));
        }
    }

    // ====== layer 2 + streaming layer 3: per n-pair, finish k then fold ======
    u64 po[2][2] = {{0ULL, 0ULL}, {0ULL, 0ULL}};   // [m][row qr / qr+8] (out0,out1)
    #pragma unroll
    for (int p = 0; p < 4; p++) {
        float D2[2][2][4];       // [m][n-subtile][frag], only this n-pair live
        #pragma unroll
        for (int q = 0; q < 2; q++) {
            int n = 2 * p + q;
            float bx = b2s[n * 8 + qc * 2], by = b2s[n * 8 + qc * 2 + 1];
            #pragma unroll
            for (int m = 0; m < 2; m++) {
                D2[m][q][0] = bx; D2[m][q][1] = by; D2[m][q][2] = bx; D2[m][q][3] = by;
            }
        }
        #pragma unroll
        for (int kt = 0; kt < 4; kt++) {
            uint32_t bh[4], bl[4];
            ldsm_x4t(bh, B_ADDR(SO_W2H, kt, p));
            ldsm_x4t(bl, B_ADDR(SO_W2L, kt, p));
            #pragma unroll
            for (int m = 0; m < 2; m++) {
                mma16816(D2[m][0], a2[kt][m], bh[0], bh[1]);
                mma16816(D2[m][0], a2[kt][m], bl[0], bl[1]);
                mma16816(D2[m][1], a2[kt][m], bh[2], bh[3]);
                mma16816(D2[m][1], a2[kt][m], bl[2], bl[3]);
            }
        }
        #pragma unroll
        for (int q = 0; q < 2; q++) {
            int n = 2 * p + q;
            u64 wa = w3p[n * 8 + qc * 2];
            u64 wb = w3p[n * 8 + qc * 2 + 1];
            #pragma unroll
            for (int m = 0; m < 2; m++) {
                ffma2(po[m][0], pack2(fmaxf(D2[m][q][0], 0.f)), wa);
                ffma2(po[m][0], pack2(fmaxf(D2[m][q][1], 0.f)), wb);
                ffma2(po[m][1], pack2(fmaxf(D2[m][q][2], 0.f)), wa);
                ffma2(po[m][1], pack2(fmaxf(D2[m][q][3], 0.f)), wb);
            }
        }
    }

    // ---- layer-3 cross-lane reduction + store ----
    #pragma unroll
    for (int m = 0; m < 2; m++) {
        #pragma unroll
        for (int h = 0; h < 2; h++) {
            float2 f = un2(po[m][h]);
            f.x += __shfl_xor_sync(0xffffffffu, f.x, 1);
            f.y += __shfl_xor_sync(0xffffffffu, f.y, 1);
            f.x += __shfl_xor_sync(0xffffffffu, f.x, 2);
            f.y += __shfl_xor_sync(0xffffffffu, f.y, 2);
            if (qc == 0) {
                int brow = brow0 + wrp * 32 + m * 16 + h * 8 + qr;
                out[(size_t)brow * 64 + k] = fminf(fmaxf(f.x + b3.x, -5.0f), 5.0f);
                out[(size_t)(BATCHN + brow) * 64 + k] = f.y + b3.y;
            }
        }
    }

    // ---- network 0: constant column (net==0 CTAs only) ----
    if (net == 0) {
        float s0 = c0[0], t0 = c0[1];
        #pragma unroll
        for (int h = 0; h < 64; h++) {
            float hv = fmaxf(w0[h] + b0[h], 0.0f);
            s0 = fmaf(hv, v0[2 * h],     s0);
            t0 = fmaf(hv, v0[2 * h + 1], t0);
        }
        const int brow = brow0 + t;
        out[(size_t)brow * 64] = fminf(fmaxf(s0, -5.0f), 5.0f);
        out[(size_t)(BATCHN + brow) * 64] = t0;
    }
}

extern "C" void kernel_launch(void* const* d_in, const int* in_sizes, int n_in,
                              void* d_out, int out_size)
{
    (void)in_sizes; (void)n_in; (void)out_size;
    const float* x  = (const float*)d_in[0];
    const float* w0 = (const float*)d_in[1];
    const float* b0 = (const float*)d_in[2];
    const float* v0 = (const float*)d_in[3];
    const float* c0 = (const float*)d_in[4];
    const float* W1 = (const float*)d_in[5];
    const float* B1 = (const float*)d_in[6];
    const float* W2 = (const float*)d_in[7];
    const float* B2 = (const float*)d_in[8];
    const float* W3 = (const float*)d_in[9];
    const float* B3 = (const float*)d_in[10];
    float* out = (float*)d_out;

    cudaFuncSetAttribute(arnet_hmma5,
                         cudaFuncAttributeMaxDynamicSharedMemorySize, SMEM_BYTES);

    prep_x<<<256, TPB>>>(x);
    prep_w<<<63, TPB>>>(W1, W2);
    dim3 grid(BATCHN / TPB, 63);   // (128, 63)
    arnet_hmma5<<<grid, TPB, SMEM_BYTES>>>(w0, b0, v0, c0,
                                           B1, B2, W3, B3, out);
}

// round 13
// speedup vs baseline: 5.4940x; 1.1531x over previous
#include <cuda_runtime.h>
#include <cuda_fp16.h>
#include <cstdint>

// AutoregressiveNetwork via HMMA mma.sync m16n8k16 fp16 + ldmatrix (sm_80 PTX;
// tcgen05 unavailable: harness emits compute_103, not 103a).
// 63 masked MLPs [B,k]->64->64->2, B=16384. CTA = (net, 128-row tile), 4 warps.
// R13: SINGLE-pass fp16 (weights rounded to fp16, no lo refinement). Calibrated
// error model from R12 (1.16e-4 with exact weights, activation-rounding bound)
// predicts ~2e-4 total -- 4x under the 1e-3 gate -- while halving the MMA count
// (104 -> 52 per warp) of a tensor-issue-bound mainloop. SMEM 33KB -> 6 CTAs/SM.

#define BATCHN 16384
#define TPB    128

#define SO_XH  0         // x fp16 : 128 rows * 128B = 16384
#define SO_W1  16384     // W1 [j][n] fp16, 64 rows * 128B = 8192 (j>=k zeroed)
#define SO_W2  24576
#define SO_W3  32768     // 64 x float2
#define SO_B1  33280     // 64 floats
#define SO_B2  33536
#define SO_B3  33792     // float2
#define SMEM_BYTES 33800

#define SW(o) ((o) ^ (((o) >> 3) & 0x70))   // SW128 swizzle (128B rows)

typedef unsigned long long u64;

// ---- precomputed swizzled fp16 images (device scratch) ----
__device__ __align__(16) char gXH[128 * 16384];   // per 128-row tile: 16KB
__device__ __align__(16) char gW1H[63 * 8192];    // per net, causal-masked
__device__ __align__(16) char gW2H[63 * 8192];

static __device__ __forceinline__ uint32_t smem_u32(const void* p) {
    uint32_t a;
    asm("{ .reg .u64 t; cvta.to.shared.u64 t, %1; cvt.u32.u64 %0, t; }" : "=r"(a) : "l"(p));
    return a;
}
static __device__ __forceinline__ u64 pack2(float x) {
    u64 r; asm("mov.b64 %0, {%1, %1};" : "=l"(r) : "f"(x)); return r;
}
static __device__ __forceinline__ void ffma2(u64& d, u64 a, u64 b) {
    asm("fma.rn.f32x2 %0, %1, %2, %0;" : "+l"(d) : "l"(a), "l"(b));
}
static __device__ __forceinline__ float2 un2(u64 a) {
    float2 f; asm("mov.b64 {%0, %1}, %2;" : "=f"(f.x), "=f"(f.y) : "l"(a)); return f;
}
static __device__ __forceinline__ uint32_t h2pack(float a, float b) {
    __half2 h = __floats2half2_rn(a, b);
    return *(uint32_t*)&h;
}
static __device__ __forceinline__ void mma16816(float* d, const uint32_t* a,
                                                uint32_t b0, uint32_t b1) {
    asm volatile(
        "mma.sync.aligned.m16n8k16.row.col.f32.f16.f16.f32 "
        "{%0,%1,%2,%3}, {%4,%5,%6,%7}, {%8,%9}, {%0,%1,%2,%3};"
        : "+f"(d[0]), "+f"(d[1]), "+f"(d[2]), "+f"(d[3])
        : "r"(a[0]), "r"(a[1]), "r"(a[2]), "r"(a[3]), "r"(b0), "r"(b1));
}
static __device__ __forceinline__ void ldsm_x4(uint32_t* r, uint32_t addr) {
    asm volatile("ldmatrix.sync.aligned.m8n8.x4.shared.b16 {%0,%1,%2,%3}, [%4];"
        : "=r"(r[0]), "=r"(r[1]), "=r"(r[2]), "=r"(r[3]) : "r"(addr));
}
static __device__ __forceinline__ void ldsm_x4t(uint32_t* r, uint32_t addr) {
    asm volatile("ldmatrix.sync.aligned.m8n8.x4.trans.shared.b16 {%0,%1,%2,%3}, [%4];"
        : "=r"(r[0]), "=r"(r[1]), "=r"(r[2]), "=r"(r[3]) : "r"(addr));
}

// ============ prep kernel 1: x -> swizzled fp16 tile images ============
__global__ void __launch_bounds__(TPB)
prep_x(const float* __restrict__ x)
{
    const int tt  = blockIdx.x >> 2;        // tile 0..127
    const int qtr = blockIdx.x & 3;         // quarter-tile
    const int t   = threadIdx.x;
    const float4* gx = (const float4*)(x + (size_t)tt * 128 * 64);
    char* dh = gXH + (size_t)tt * 16384;
    #pragma unroll
    for (int i = 0; i < 4; i++) {
        int idx = qtr * 512 + t + i * TPB;   // 0..2047 float4s
        int r = idx >> 4, q = idx & 15;
        float4 v = gx[idx];
        __half2 p0 = __floats2half2_rn(v.x, v.y);
        __half2 p1 = __floats2half2_rn(v.z, v.w);
        int off = SW(r * 128 + q * 8);
        *(uint2*)(dh + off) = make_uint2(*(uint32_t*)&p0, *(uint32_t*)&p1);
    }
}

// ====== prep kernel 2: W1 (causal-masked) / W2 -> swizzled fp16 images ======
__global__ void __launch_bounds__(TPB)
prep_w(const float* __restrict__ W1, const float* __restrict__ W2)
{
    const int net = blockIdx.x;          // 0..62, k = net+1
    const int k   = net + 1;
    const int t   = threadIdx.x;
    const float4* g1 = (const float4*)(W1 + (size_t)net * 4096);
    const float4* g2 = (const float4*)(W2 + (size_t)net * 4096);
    char* d1 = gW1H + (size_t)net * 8192;
    char* d2 = gW2H + (size_t)net * 8192;
    #pragma unroll
    for (int i = 0; i < 8; i++) {
        int i4 = t + i * TPB;            // 0..1023; (j, 4 n's)
        int j = i4 >> 4, n4 = i4 & 15;
        float4 v1 = g1[i4];
        float4 v2 = g2[i4];
        if (j >= k) { v1.x = v1.y = v1.z = v1.w = 0.0f; }   // causal mask
        int off = SW(j * 128 + n4 * 8);
        *(uint2*)(d1 + off) = make_uint2(h2pack(v1.x, v1.y), h2pack(v1.z, v1.w));
        *(uint2*)(d2 + off) = make_uint2(h2pack(v2.x, v2.y), h2pack(v2.z, v2.w));
    }
}

// ============================== main kernel ==================================
__global__ void __launch_bounds__(TPB, 6)
arnet_hmma6(const float* __restrict__ w0, const float* __restrict__ b0,
            const float* __restrict__ v0, const float* __restrict__ c0,
            const float* __restrict__ B1, const float* __restrict__ B2,
            const float* __restrict__ W3, const float* __restrict__ B3,
            float* __restrict__ out)
{
    extern __shared__ char smc[];
    const uint32_t sb = smem_u32(smc);
    const int t    = threadIdx.x;
    const int lane = t & 31;
    const int wrp  = t >> 5;
    const int qr   = lane >> 2;     // 0..7
    const int qc   = lane & 3;      // 0..3
    const int lm   = lane >> 3;     // ldmatrix sub-matrix id 0..3
    const int lr8  = lane & 7;      // ldmatrix row-within-matrix
    const int net  = blockIdx.y;    // network k = net+1
    const int k    = net + 1;
    const int brow0 = blockIdx.x * TPB;

    // ---- staging = verbatim float4 copies of precomputed images ----
    {
        const float4* sxh = (const float4*)(gXH + (size_t)blockIdx.x * 16384);
        float4* dxh = (float4*)(smc + SO_XH);
        #pragma unroll
        for (int i = 0; i < 8; i++)
            dxh[t + i * TPB] = sxh[t + i * TPB];
        const float4* s1 = (const float4*)(gW1H + (size_t)net * 8192);
        const float4* s2 = (const float4*)(gW2H + (size_t)net * 8192);
        float4* d1 = (float4*)(smc + SO_W1);
        float4* d2 = (float4*)(smc + SO_W2);
        #pragma unroll
        for (int i = 0; i < 4; i++) {
            d1[t + i * TPB] = s1[t + i * TPB];
            d2[t + i * TPB] = s2[t + i * TPB];
        }
        if (t < 64) {
            ((float*)(smc + SO_B1))[t] = B1[net * 64 + t];
            ((float*)(smc + SO_B2))[t] = B2[net * 64 + t];
            ((float2*)(smc + SO_W3))[t] =
                make_float2(W3[(size_t)net * 128 + 2 * t], W3[(size_t)net * 128 + 2 * t + 1]);
        }
        if (t == 0)
            *((float2*)(smc + SO_B3)) = make_float2(B3[net * 2], B3[net * 2 + 1]);
    }
    __syncthreads();

    const float* b1s = (const float*)(smc + SO_B1);
    const float* b2s = (const float*)(smc + SO_B2);
    const u64*   w3p = (const u64*)(smc + SO_W3);
    const float2 b3  = *(const float2*)(smc + SO_B3);
    const int kt1 = (k + 15) >> 4;     // causal trim of layer-1 k-tiles

    #define A_ADDR(base, m, kt) \
        (sb + (base) + SW((wrp * 32 + (m) * 16 + (lm & 1) * 8 + lr8) * 128 + (kt) * 32 + (lm >> 1) * 16))
    #define B_ADDR(base, kt, p) \
        (sb + (base) + SW(((kt) * 16 + (lm & 1) * 8 + lr8) * 128 + ((p) * 2 + (lm >> 1)) * 16))

    // ====== layer 1: D1 = x[:, :k] @ W1 + B1  (single fp16 pass, 32 rows) ======
    float D1[2][8][4];          // [m][n-tile][frag]
    #pragma unroll
    for (int n = 0; n < 8; n++) {
        float bx = b1s[n * 8 + qc * 2], by = b1s[n * 8 + qc * 2 + 1];
        #pragma unroll
        for (int m = 0; m < 2; m++) {
            D1[m][n][0] = bx; D1[m][n][1] = by; D1[m][n][2] = bx; D1[m][n][3] = by;
        }
    }
    for (int kt = 0; kt < kt1; kt++) {
        uint32_t a[2][4];
        ldsm_x4(a[0], A_ADDR(SO_XH, 0, kt));
        ldsm_x4(a[1], A_ADDR(SO_XH, 1, kt));
        #pragma unroll
        for (int p = 0; p < 4; p++) {
            uint32_t bh[4];
            ldsm_x4t(bh, B_ADDR(SO_W1, kt, p));
            #pragma unroll
            for (int m = 0; m < 2; m++) {
                mma16816(D1[m][2 * p],     a[m], bh[0], bh[1]);
                mma16816(D1[m][2 * p + 1], a[m], bh[2], bh[3]);
            }
        }
    }

    // ---- relu + fp16-round D1 -> persistent layer-2 A fragments ----
    uint32_t a2[4][2][4];       // [kt][m][frag]
    #pragma unroll
    for (int kt = 0; kt < 4; kt++) {
        #pragma unroll
        for (int m = 0; m < 2; m++) {
            a2[kt][m][0] = h2pack(fmaxf(D1[m][2*kt  ][0], 0.f), fmaxf(D1[m][2*kt  ][1], 0.f));
            a2[kt][m][1] = h2pack(fmaxf(D1[m][2*kt  ][2], 0.f), fmaxf(D1[m][2*kt  ][3], 0.f));
            a2[kt][m][2] = h2pack(fmaxf(D1[m][2*kt+1][0], 0.f), fmaxf(D1[m][2*kt+1][1], 0.f));
            a2[kt][m][3] = h2pack(fmaxf(D1[m][2*kt+1][2], 0.f), fmaxf(D1[m][2*kt+1][3], 0.f));
        }
    }

    // ====== layer 2 + streaming layer 3: per n-pair, finish k then fold ======
    u64 po[2][2] = {{0ULL, 0ULL}, {0ULL, 0ULL}};   // [m][row qr / qr+8] (out0,out1)
    #pragma unroll
    for (int p = 0; p < 4; p++) {
        float D2[2][2][4];       // [m][n-subtile][frag], only this n-pair live
        #pragma unroll
        for (int q = 0; q < 2; q++) {
            int n = 2 * p + q;
            float bx = b2s[n * 8 + qc * 2], by = b2s[n * 8 + qc * 2 + 1];
            #pragma unroll
            for (int m = 0; m < 2; m++) {
                D2[m][q][0] = bx; D2[m][q][1] = by; D2[m][q][2] = bx; D2[m][q][3] = by;
            }
        }
        #pragma unroll
        for (int kt = 0; kt < 4; kt++) {
            uint32_t bh[4];
            ldsm_x4t(bh, B_ADDR(SO_W2, kt, p));
            #pragma unroll
            for (int m = 0; m < 2; m++) {
                mma16816(D2[m][0], a2[kt][m], bh[0], bh[1]);
                mma16816(D2[m][1], a2[kt][m], bh[2], bh[3]);
            }
        }
        #pragma unroll
        for (int q = 0; q < 2; q++) {
            int n = 2 * p + q;
            u64 wa = w3p[n * 8 + qc * 2];
            u64 wb = w3p[n * 8 + qc * 2 + 1];
            #pragma unroll
            for (int m = 0; m < 2; m++) {
                ffma2(po[m][0], pack2(fmaxf(D2[m][q][0], 0.f)), wa);
                ffma2(po[m][0], pack2(fmaxf(D2[m][q][1], 0.f)), wb);
                ffma2(po[m][1], pack2(fmaxf(D2[m][q][2], 0.f)), wa);
                ffma2(po[m][1], pack2(fmaxf(D2[m][q][3], 0.f)), wb);
            }
        }
    }

    // ---- layer-3 cross-lane reduction + store ----
    #pragma unroll
    for (int m = 0; m < 2; m++) {
        #pragma unroll
        for (int h = 0; h < 2; h++) {
            float2 f = un2(po[m][h]);
            f.x += __shfl_xor_sync(0xffffffffu, f.x, 1);
            f.y += __shfl_xor_sync(0xffffffffu, f.y, 1);
            f.x += __shfl_xor_sync(0xffffffffu, f.x, 2);
            f.y += __shfl_xor_sync(0xffffffffu, f.y, 2);
            if (qc == 0) {
                int brow = brow0 + wrp * 32 + m * 16 + h * 8 + qr;
                out[(size_t)brow * 64 + k] = fminf(fmaxf(f.x + b3.x, -5.0f), 5.0f);
                out[(size_t)(BATCHN + brow) * 64 + k] = f.y + b3.y;
            }
        }
    }

    // ---- network 0: constant column (net==0 CTAs only) ----
    if (net == 0) {
        float s0 = c0[0], t0 = c0[1];
        #pragma unroll
        for (int h = 0; h < 64; h++) {
            float hv = fmaxf(w0[h] + b0[h], 0.0f);
            s0 = fmaf(hv, v0[2 * h],     s0);
            t0 = fmaf(hv, v0[2 * h + 1], t0);
        }
        const int brow = brow0 + t;
        out[(size_t)brow * 64] = fminf(fmaxf(s0, -5.0f), 5.0f);
        out[(size_t)(BATCHN + brow) * 64] = t0;
    }
}

extern "C" void kernel_launch(void* const* d_in, const int* in_sizes, int n_in,
                              void* d_out, int out_size)
{
    (void)in_sizes; (void)n_in; (void)out_size;
    const float* x  = (const float*)d_in[0];
    const float* w0 = (const float*)d_in[1];
    const float* b0 = (const float*)d_in[2];
    const float* v0 = (const float*)d_in[3];
    const float* c0 = (const float*)d_in[4];
    const float* W1 = (const float*)d_in[5];
    const float* B1 = (const float*)d_in[6];
    const float* W2 = (const float*)d_in[7];
    const float* B2 = (const float*)d_in[8];
    const float* W3 = (const float*)d_in[9];
    const float* B3 = (const float*)d_in[10];
    float* out = (float*)d_out;

    cudaFuncSetAttribute(arnet_hmma6,
                         cudaFuncAttributeMaxDynamicSharedMemorySize, SMEM_BYTES);

    prep_x<<<512, TPB>>>(x);
    prep_w<<<63, TPB>>>(W1, W2);
    dim3 grid(BATCHN / TPB, 63);   // (128, 63)
    arnet_hmma6<<<grid, TPB, SMEM_BYTES>>>(w0, b0, v0, c0,
                                           B1, B2, W3, B3, out);
}

// round 14
// speedup vs baseline: 8.3996x; 1.5289x over previous
#include <cuda_runtime.h>
#include <cuda_fp16.h>
#include <cstdint>

// AutoregressiveNetwork via HMMA mma.sync m16n8k16 fp16 + ldmatrix (sm_80 PTX;
// tcgen05 unavailable at compute_103).
// R14: (1) launch_bounds(128,3) -- R12/R13's (128,6) capped regs at 85 and
// spilled ~80 floats of accumulators to local memory (the hidden L1 load);
// (2) layer 3 via MMA (D2-frag == A-frag identity, W3 as 64x16 fp16 image)
// replacing the ~200-instr scalar epilogue; (3) cp.async.bulk staging (4 bulk
// copies + mbarrier) replacing 32 LDG/STS per thread.

#define BATCHN 16384
#define TPB    128

#define SO_XH   0        // x fp16 : 128 rows * 128B = 16384
#define SO_W1   16384    // W1 [j][n] fp16, 8192 (j>=k zeroed)
#define SO_W2   24576    // 8192
#define SO_W3F  32768    // W3 fp16 image: 64 rows * 32B = 2048 (cols>=2 zero)
#define SO_B1   34816    // 64 floats
#define SO_B2   35072
#define SO_B3   35328    // float2
#define SO_MBAR 35336
#define SMEM_BYTES 35344
#define BULK_BYTES (16384 + 8192 + 8192 + 2048)

#define SW(o) ((o) ^ (((o) >> 3) & 0x70))   // SW128 swizzle (128B rows)

typedef unsigned long long u64;

// ---- precomputed swizzled fp16 images (device scratch) ----
__device__ __align__(16) char gXH[128 * 16384];   // per 128-row tile
__device__ __align__(16) char gW1H[63 * 8192];    // per net, causal-masked
__device__ __align__(16) char gW2H[63 * 8192];
__device__ __align__(16) char gW3F[63 * 2048];    // per net, L3 B image

static __device__ __forceinline__ uint32_t smem_u32(const void* p) {
    uint32_t a;
    asm("{ .reg .u64 t; cvta.to.shared.u64 t, %1; cvt.u32.u64 %0, t; }" : "=r"(a) : "l"(p));
    return a;
}
static __device__ __forceinline__ uint32_t h2pack(float a, float b) {
    __half2 h = __floats2half2_rn(a, b);
    return *(uint32_t*)&h;
}
static __device__ __forceinline__ void mma16816(float* d, const uint32_t* a,
                                                uint32_t b0, uint32_t b1) {
    asm volatile(
        "mma.sync.aligned.m16n8k16.row.col.f32.f16.f16.f32 "
        "{%0,%1,%2,%3}, {%4,%5,%6,%7}, {%8,%9}, {%0,%1,%2,%3};"
        : "+f"(d[0]), "+f"(d[1]), "+f"(d[2]), "+f"(d[3])
        : "r"(a[0]), "r"(a[1]), "r"(a[2]), "r"(a[3]), "r"(b0), "r"(b1));
}
static __device__ __forceinline__ void ldsm_x4(uint32_t* r, uint32_t addr) {
    asm volatile("ldmatrix.sync.aligned.m8n8.x4.shared.b16 {%0,%1,%2,%3}, [%4];"
        : "=r"(r[0]), "=r"(r[1]), "=r"(r[2]), "=r"(r[3]) : "r"(addr));
}
static __device__ __forceinline__ void ldsm_x4t(uint32_t* r, uint32_t addr) {
    asm volatile("ldmatrix.sync.aligned.m8n8.x4.trans.shared.b16 {%0,%1,%2,%3}, [%4];"
        : "=r"(r[0]), "=r"(r[1]), "=r"(r[2]), "=r"(r[3]) : "r"(addr));
}
static __device__ __forceinline__ void bulk_cp(uint32_t dst, const void* src,
                                               uint32_t bytes, uint32_t mbar) {
    asm volatile(
        "cp.async.bulk.shared::cluster.global.mbarrier::complete_tx::bytes "
        "[%0], [%1], %2, [%3];"
        :: "r"(dst), "l"(src), "r"(bytes), "r"(mbar) : "memory");
}
#define MB_INIT(mb, c) asm volatile("mbarrier.init.shared.b64 [%0], %1;" :: "r"(mb), "r"((uint32_t)(c)) : "memory")
#define MB_EXPECT(mb, n) asm volatile("mbarrier.arrive.expect_tx.shared.b64 _, [%0], %1;" :: "r"(mb), "r"((uint32_t)(n)) : "memory")
#define MB_WAIT(mb, par) do {                                                    \
    uint32_t _m = (mb), _p = (par), _d;                                          \
    asm volatile("{\n\t.reg .pred p;\n\t"                                        \
        "mbarrier.try_wait.parity.acquire.cta.shared::cta.b64 p, [%1], %2;\n\t"  \
        "selp.b32 %0,1,0,p;\n\t}" : "=r"(_d) : "r"(_m), "r"(_p) : "memory");     \
    if (!_d) {                                                                   \
        asm volatile("{\n\t.reg .pred P1;\n\tWL_%=:\n\t"                         \
            "mbarrier.try_wait.parity.acquire.cta.shared::cta.b64 P1, [%0], %1, 0x989680;\n\t" \
            "@P1 bra.uni WD_%=;\n\tbra.uni WL_%=;\n\tWD_%=:\n\t}"                \
            :: "r"(_m), "r"(_p) : "memory");                                     \
    }                                                                            \
} while (0)

// ============ prep kernel 1: x -> swizzled fp16 tile images ============
__global__ void __launch_bounds__(TPB)
prep_x(const float* __restrict__ x)
{
    const int tt  = blockIdx.x >> 2;        // tile 0..127
    const int qtr = blockIdx.x & 3;
    const int t   = threadIdx.x;
    const float4* gx = (const float4*)(x + (size_t)tt * 128 * 64);
    char* dh = gXH + (size_t)tt * 16384;
    #pragma unroll
    for (int i = 0; i < 4; i++) {
        int idx = qtr * 512 + t + i * TPB;
        int r = idx >> 4, q = idx & 15;
        float4 v = gx[idx];
        int off = SW(r * 128 + q * 8);
        *(uint2*)(dh + off) = make_uint2(h2pack(v.x, v.y), h2pack(v.z, v.w));
    }
}

// == prep kernel 2: W1 (masked) / W2 -> swizzled fp16; W3 -> L3 B image ==
__global__ void __launch_bounds__(TPB)
prep_w(const float* __restrict__ W1, const float* __restrict__ W2,
       const float* __restrict__ W3)
{
    const int net = blockIdx.x;          // 0..62, k = net+1
    const int k   = net + 1;
    const int t   = threadIdx.x;
    const float4* g1 = (const float4*)(W1 + (size_t)net * 4096);
    const float4* g2 = (const float4*)(W2 + (size_t)net * 4096);
    char* d1 = gW1H + (size_t)net * 8192;
    char* d2 = gW2H + (size_t)net * 8192;
    #pragma unroll
    for (int i = 0; i < 8; i++) {
        int i4 = t + i * TPB;            // 0..1023; (j, 4 n's)
        int j = i4 >> 4, n4 = i4 & 15;
        float4 v1 = g1[i4];
        float4 v2 = g2[i4];
        if (j >= k) { v1.x = v1.y = v1.z = v1.w = 0.0f; }   // causal mask
        int off = SW(j * 128 + n4 * 8);
        *(uint2*)(d1 + off) = make_uint2(h2pack(v1.x, v1.y), h2pack(v1.z, v1.w));
        *(uint2*)(d2 + off) = make_uint2(h2pack(v2.x, v2.y), h2pack(v2.z, v2.w));
    }
    // W3 image: row j (h2 index) 32B: cols0,1 = W3[j][0..1] fp16, rest zero
    if (t < 64) {
        char* d3 = gW3F + (size_t)net * 2048 + t * 32;
        float a = W3[(size_t)net * 128 + 2 * t];
        float b = W3[(size_t)net * 128 + 2 * t + 1];
        *(uint4*)(d3)      = make_uint4(h2pack(a, b), 0u, 0u, 0u);
        *(uint4*)(d3 + 16) = make_uint4(0u, 0u, 0u, 0u);
    }
}

// ============================== main kernel ==================================
__global__ void __launch_bounds__(TPB, 3)
arnet_hmma7(const float* __restrict__ w0, const float* __restrict__ b0,
            const float* __restrict__ v0, const float* __restrict__ c0,
            const float* __restrict__ B1, const float* __restrict__ B2,
            const float* __restrict__ B3,
            float* __restrict__ out)
{
    extern __shared__ char smc[];
    const uint32_t sb = smem_u32(smc);
    const int t    = threadIdx.x;
    const int lane = t & 31;
    const int wrp  = t >> 5;
    const int qr   = lane >> 2;     // 0..7
    const int qc   = lane & 3;      // 0..3
    const int lm   = lane >> 3;     // ldmatrix sub-matrix id 0..3
    const int lr8  = lane & 7;      // ldmatrix row-within-matrix
    const int net  = blockIdx.y;    // network k = net+1
    const int k    = net + 1;
    const int brow0 = blockIdx.x * TPB;

    // ---- async bulk staging of precomputed images ----
    if (t == 0) {
        MB_INIT(sb + SO_MBAR, 1);
        // fence init->expect handled by same-thread program order
        MB_EXPECT(sb + SO_MBAR, BULK_BYTES);
        bulk_cp(sb + SO_XH,  gXH  + (size_t)blockIdx.x * 16384, 16384, sb + SO_MBAR);
        bulk_cp(sb + SO_W1,  gW1H + (size_t)net * 8192,  8192, sb + SO_MBAR);
        bulk_cp(sb + SO_W2,  gW2H + (size_t)net * 8192,  8192, sb + SO_MBAR);
        bulk_cp(sb + SO_W3F, gW3F + (size_t)net * 2048,  2048, sb + SO_MBAR);
    }
    // small scalar tables
    if (t < 64) {
        ((float*)(smc + SO_B1))[t] = B1[net * 64 + t];
        ((float*)(smc + SO_B2))[t] = B2[net * 64 + t];
    }
    if (t == 64)
        *((float2*)(smc + SO_B3)) = make_float2(B3[net * 2], B3[net * 2 + 1]);
    __syncthreads();
    MB_WAIT(sb + SO_MBAR, 0);

    const float* b1s = (const float*)(smc + SO_B1);
    const float* b2s = (const float*)(smc + SO_B2);
    const float2 b3  = *(const float2*)(smc + SO_B3);
    const int kt1 = (k + 15) >> 4;     // causal trim of layer-1 k-tiles

    #define A_ADDR(base, m, kt) \
        (sb + (base) + SW((wrp * 32 + (m) * 16 + (lm & 1) * 8 + lr8) * 128 + (kt) * 32 + (lm >> 1) * 16))
    #define B_ADDR(base, kt, p) \
        (sb + (base) + SW(((kt) * 16 + (lm & 1) * 8 + lr8) * 128 + ((p) * 2 + (lm >> 1)) * 16))

    // ====== layer 1: D1 = x[:, :k] @ W1 + B1 (single fp16 pass, 32 rows) ======
    float D1[2][8][4];          // [m][n-tile][frag]
    #pragma unroll
    for (int n = 0; n < 8; n++) {
        float bx = b1s[n * 8 + qc * 2], by = b1s[n * 8 + qc * 2 + 1];
        #pragma unroll
        for (int m = 0; m < 2; m++) {
            D1[m][n][0] = bx; D1[m][n][1] = by; D1[m][n][2] = bx; D1[m][n][3] = by;
        }
    }
    for (int kt = 0; kt < kt1; kt++) {
        uint32_t a[2][4];
        ldsm_x4(a[0], A_ADDR(SO_XH, 0, kt));
        ldsm_x4(a[1], A_ADDR(SO_XH, 1, kt));
        #pragma unroll
        for (int p = 0; p < 4; p++) {
            uint32_t bh[4];
            ldsm_x4t(bh, B_ADDR(SO_W1, kt, p));
            #pragma unroll
            for (int m = 0; m < 2; m++) {
                mma16816(D1[m][2 * p],     a[m], bh[0], bh[1]);
                mma16816(D1[m][2 * p + 1], a[m], bh[2], bh[3]);
            }
        }
    }

    // ---- relu + fp16-round D1 -> persistent layer-2 A fragments ----
    uint32_t a2[4][2][4];       // [kt][m][frag]
    #pragma unroll
    for (int kt = 0; kt < 4; kt++) {
        #pragma unroll
        for (int m = 0; m < 2; m++) {
            a2[kt][m][0] = h2pack(fmaxf(D1[m][2*kt  ][0], 0.f), fmaxf(D1[m][2*kt  ][1], 0.f));
            a2[kt][m][1] = h2pack(fmaxf(D1[m][2*kt  ][2], 0.f), fmaxf(D1[m][2*kt  ][3], 0.f));
            a2[kt][m][2] = h2pack(fmaxf(D1[m][2*kt+1][0], 0.f), fmaxf(D1[m][2*kt+1][1], 0.f));
            a2[kt][m][3] = h2pack(fmaxf(D1[m][2*kt+1][2], 0.f), fmaxf(D1[m][2*kt+1][3], 0.f));
        }
    }

    // ====== layer 2 + MMA layer 3: n-pair p of L2 == k-tile p of L3 ======
    float D3[2][4];             // [m][frag]; cols 0,1 = (out0,out1)
    #pragma unroll
    for (int m = 0; m < 2; m++) {
        D3[m][0] = b3.x; D3[m][1] = b3.y; D3[m][2] = b3.x; D3[m][3] = b3.y;
    }
    #pragma unroll
    for (int p = 0; p < 4; p++) {
        float D2[2][2][4];       // [m][n-subtile][frag], only this n-pair live
        #pragma unroll
        for (int q = 0; q < 2; q++) {
            int n = 2 * p + q;
            float bx = b2s[n * 8 + qc * 2], by = b2s[n * 8 + qc * 2 + 1];
            #pragma unroll
            for (int m = 0; m < 2; m++) {
                D2[m][q][0] = bx; D2[m][q][1] = by; D2[m][q][2] = bx; D2[m][q][3] = by;
            }
        }
        #pragma unroll
        for (int kt = 0; kt < 4; kt++) {
            uint32_t bh[4];
            ldsm_x4t(bh, B_ADDR(SO_W2, kt, p));
            #pragma unroll
            for (int m = 0; m < 2; m++) {
                mma16816(D2[m][0], a2[kt][m], bh[0], bh[1]);
                mma16816(D2[m][1], a2[kt][m], bh[2], bh[3]);
            }
        }
        // relu + pack -> L3 A-fragment for k-tile p; fold into D3 via MMA
        uint32_t b3f[4];
        ldsm_x4t(b3f, sb + SO_W3F + (p * 16 + (lm & 1) * 8 + lr8) * 32 + (lm >> 1) * 16);
        #pragma unroll
        for (int m = 0; m < 2; m++) {
            uint32_t a3[4];
            a3[0] = h2pack(fmaxf(D2[m][0][0], 0.f), fmaxf(D2[m][0][1], 0.f));
            a3[1] = h2pack(fmaxf(D2[m][0][2], 0.f), fmaxf(D2[m][0][3], 0.f));
            a3[2] = h2pack(fmaxf(D2[m][1][0], 0.f), fmaxf(D2[m][1][1], 0.f));
            a3[3] = h2pack(fmaxf(D2[m][1][2], 0.f), fmaxf(D2[m][1][3], 0.f));
            mma16816(D3[m], a3, b3f[0], b3f[1]);
        }
    }

    // ---- store: qc==0 lanes hold cols 0,1 = (out0,out1) ----
    if (qc == 0) {
        #pragma unroll
        for (int m = 0; m < 2; m++) {
            int brow = brow0 + wrp * 32 + m * 16 + qr;
            out[(size_t)brow * 64 + k] = fminf(fmaxf(D3[m][0], -5.0f), 5.0f);
            out[(size_t)(BATCHN + brow) * 64 + k] = D3[m][1];
            out[(size_t)(brow + 8) * 64 + k] = fminf(fmaxf(D3[m][2], -5.0f), 5.0f);
            out[(size_t)(BATCHN + brow + 8) * 64 + k] = D3[m][3];
        }
    }

    // ---- network 0: constant column (net==0 CTAs only) ----
    if (net == 0) {
        float s0 = c0[0], t0 = c0[1];
        #pragma unroll
        for (int h = 0; h < 64; h++) {
            float hv = fmaxf(w0[h] + b0[h], 0.0f);
            s0 = fmaf(hv, v0[2 * h],     s0);
            t0 = fmaf(hv, v0[2 * h + 1], t0);
        }
        const int brow = brow0 + t;
        out[(size_t)brow * 64] = fminf(fmaxf(s0, -5.0f), 5.0f);
        out[(size_t)(BATCHN + brow) * 64] = t0;
    }
}

extern "C" void kernel_launch(void* const* d_in, const int* in_sizes, int n_in,
                              void* d_out, int out_size)
{
    (void)in_sizes; (void)n_in; (void)out_size;
    const float* x  = (const float*)d_in[0];
    const float* w0 = (const float*)d_in[1];
    const float* b0 = (const float*)d_in[2];
    const float* v0 = (const float*)d_in[3];
    const float* c0 = (const float*)d_in[4];
    const float* W1 = (const float*)d_in[5];
    const float* B1 = (const float*)d_in[6];
    const float* W2 = (const float*)d_in[7];
    const float* B2 = (const float*)d_in[8];
    const float* W3 = (const float*)d_in[9];
    const float* B3 = (const float*)d_in[10];
    float* out = (float*)d_out;

    cudaFuncSetAttribute(arnet_hmma7,
                         cudaFuncAttributeMaxDynamicSharedMemorySize, SMEM_BYTES);

    prep_x<<<512, TPB>>>(x);
    prep_w<<<63, TPB>>>(W1, W2, W3);
    dim3 grid(BATCHN / TPB, 63);   // (128, 63)
    arnet_hmma7<<<grid, TPB, SMEM_BYTES>>>(w0, b0, v0, c0,
                                           B1, B2, B3, out);
}

// round 15
// speedup vs baseline: 9.0870x; 1.0818x over previous
#include <cuda_runtime.h>
#include <cuda_fp16.h>
#include <cstdint>

// AutoregressiveNetwork via HMMA mma.sync m16n8k16 fp16 + ldmatrix (sm_80 PTX;
// tcgen05 unavailable at compute_103). 63 masked MLPs [B,k]->64->64->2.
// R15: CTA = (net, 256 rows) processed as two 128-row halves -> weight images
// staged once per 2 row-tiles (L2 staging traffic 280->~190MB), W1 bulk copy
// trimmed to kt1*2KB (masked rows are zeros layer-1 never reads), both x halves
// prefetched up-front on separate mbarriers so half-1 staging overlaps half-0
// compute. Register footprint per warp unchanged (3 CTAs/SM, 12 warps).

#define BATCHN 16384
#define TPB    128

#define SO_XH0  0        // x half0 fp16 : 128 rows * 128B
#define SO_XH1  16384    // x half1
#define SO_W1   32768    // W1 [j][n] fp16 (j>=k zeroed); only kt1*2KB copied
#define SO_W2   40960    // 8192
#define SO_W3F  49152    // W3 fp16 image: 64 rows * 32B (cols>=2 zero)
#define SO_B1   51200    // 64 floats
#define SO_B2   51456
#define SO_B3   51712    // float2
#define SO_MB0  51720
#define SO_MB1  51728
#define SMEM_BYTES 51736

#define SW(o) ((o) ^ (((o) >> 3) & 0x70))   // SW128 swizzle (128B rows)

typedef unsigned long long u64;

// ---- precomputed swizzled fp16 images (device scratch) ----
__device__ __align__(16) char gXH[128 * 16384];   // per 128-row tile
__device__ __align__(16) char gW1H[63 * 8192];    // per net, causal-masked
__device__ __align__(16) char gW2H[63 * 8192];
__device__ __align__(16) char gW3F[63 * 2048];    // per net, L3 B image

static __device__ __forceinline__ uint32_t smem_u32(const void* p) {
    uint32_t a;
    asm("{ .reg .u64 t; cvta.to.shared.u64 t, %1; cvt.u32.u64 %0, t; }" : "=r"(a) : "l"(p));
    return a;
}
static __device__ __forceinline__ uint32_t h2pack(float a, float b) {
    __half2 h = __floats2half2_rn(a, b);
    return *(uint32_t*)&h;
}
static __device__ __forceinline__ void mma16816(float* d, const uint32_t* a,
                                                uint32_t b0, uint32_t b1) {
    asm volatile(
        "mma.sync.aligned.m16n8k16.row.col.f32.f16.f16.f32 "
        "{%0,%1,%2,%3}, {%4,%5,%6,%7}, {%8,%9}, {%0,%1,%2,%3};"
        : "+f"(d[0]), "+f"(d[1]), "+f"(d[2]), "+f"(d[3])
        : "r"(a[0]), "r"(a[1]), "r"(a[2]), "r"(a[3]), "r"(b0), "r"(b1));
}
static __device__ __forceinline__ void ldsm_x4(uint32_t* r, uint32_t addr) {
    asm volatile("ldmatrix.sync.aligned.m8n8.x4.shared.b16 {%0,%1,%2,%3}, [%4];"
        : "=r"(r[0]), "=r"(r[1]), "=r"(r[2]), "=r"(r[3]) : "r"(addr));
}
static __device__ __forceinline__ void ldsm_x4t(uint32_t* r, uint32_t addr) {
    asm volatile("ldmatrix.sync.aligned.m8n8.x4.trans.shared.b16 {%0,%1,%2,%3}, [%4];"
        : "=r"(r[0]), "=r"(r[1]), "=r"(r[2]), "=r"(r[3]) : "r"(addr));
}
static __device__ __forceinline__ void bulk_cp(uint32_t dst, const void* src,
                                               uint32_t bytes, uint32_t mbar) {
    asm volatile(
        "cp.async.bulk.shared::cluster.global.mbarrier::complete_tx::bytes "
        "[%0], [%1], %2, [%3];"
        :: "r"(dst), "l"(src), "r"(bytes), "r"(mbar) : "memory");
}
#define MB_INIT(mb, c) asm volatile("mbarrier.init.shared.b64 [%0], %1;" :: "r"(mb), "r"((uint32_t)(c)) : "memory")
#define MB_EXPECT(mb, n) asm volatile("mbarrier.arrive.expect_tx.shared.b64 _, [%0], %1;" :: "r"(mb), "r"((uint32_t)(n)) : "memory")
#define MB_WAIT(mb, par) do {                                                    \
    uint32_t _m = (mb), _p = (par), _d;                                          \
    asm volatile("{\n\t.reg .pred p;\n\t"                                        \
        "mbarrier.try_wait.parity.acquire.cta.shared::cta.b64 p, [%1], %2;\n\t"  \
        "selp.b32 %0,1,0,p;\n\t}" : "=r"(_d) : "r"(_m), "r"(_p) : "memory");     \
    if (!_d) {                                                                   \
        asm volatile("{\n\t.reg .pred P1;\n\tWL_%=:\n\t"                         \
            "mbarrier.try_wait.parity.acquire.cta.shared::cta.b64 P1, [%0], %1, 0x989680;\n\t" \
            "@P1 bra.uni WD_%=;\n\tbra.uni WL_%=;\n\tWD_%=:\n\t}"                \
            :: "r"(_m), "r"(_p) : "memory");                                     \
    }                                                                            \
} while (0)

// ============ prep kernel 1: x -> swizzled fp16 tile images ============
__global__ void __launch_bounds__(TPB)
prep_x(const float* __restrict__ x)
{
    const int tt  = blockIdx.x >> 3;        // tile 0..127
    const int oct = blockIdx.x & 7;
    const int t   = threadIdx.x;
    const float4* gx = (const float4*)(x + (size_t)tt * 128 * 64);
    char* dh = gXH + (size_t)tt * 16384;
    #pragma unroll
    for (int i = 0; i < 2; i++) {
        int idx = oct * 256 + t + i * TPB;
        int r = idx >> 4, q = idx & 15;
        float4 v = gx[idx];
        int off = SW(r * 128 + q * 8);
        *(uint2*)(dh + off) = make_uint2(h2pack(v.x, v.y), h2pack(v.z, v.w));
    }
}

// == prep kernel 2: W1 (masked) / W2 -> swizzled fp16; W3 -> L3 B image ==
__global__ void __launch_bounds__(TPB)
prep_w(const float* __restrict__ W1, const float* __restrict__ W2,
       const float* __restrict__ W3)
{
    const int net = blockIdx.x;          // 0..62, k = net+1
    const int k   = net + 1;
    const int t   = threadIdx.x;
    const float4* g1 = (const float4*)(W1 + (size_t)net * 4096);
    const float4* g2 = (const float4*)(W2 + (size_t)net * 4096);
    char* d1 = gW1H + (size_t)net * 8192;
    char* d2 = gW2H + (size_t)net * 8192;
    #pragma unroll
    for (int i = 0; i < 8; i++) {
        int i4 = t + i * TPB;            // 0..1023; (j, 4 n's)
        int j = i4 >> 4, n4 = i4 & 15;
        float4 v1 = g1[i4];
        float4 v2 = g2[i4];
        if (j >= k) { v1.x = v1.y = v1.z = v1.w = 0.0f; }   // causal mask
        int off = SW(j * 128 + n4 * 8);
        *(uint2*)(d1 + off) = make_uint2(h2pack(v1.x, v1.y), h2pack(v1.z, v1.w));
        *(uint2*)(d2 + off) = make_uint2(h2pack(v2.x, v2.y), h2pack(v2.z, v2.w));
    }
    // W3 image: row j (h2 index) 32B: cols0,1 = W3[j][0..1] fp16, rest zero
    if (t < 64) {
        char* d3 = gW3F + (size_t)net * 2048 + t * 32;
        float a = W3[(size_t)net * 128 + 2 * t];
        float b = W3[(size_t)net * 128 + 2 * t + 1];
        *(uint4*)(d3)      = make_uint4(h2pack(a, b), 0u, 0u, 0u);
        *(uint4*)(d3 + 16) = make_uint4(0u, 0u, 0u, 0u);
    }
}

// ============================== main kernel ==================================
__global__ void __launch_bounds__(TPB, 3)
arnet_hmma8(const float* __restrict__ w0, const float* __restrict__ b0,
            const float* __restrict__ v0, const float* __restrict__ c0,
            const float* __restrict__ B1, const float* __restrict__ B2,
            const float* __restrict__ B3,
            float* __restrict__ out)
{
    extern __shared__ char smc[];
    const uint32_t sb = smem_u32(smc);
    const int t    = threadIdx.x;
    const int lane = t & 31;
    const int wrp  = t >> 5;
    const int qr   = lane >> 2;     // 0..7
    const int qc   = lane & 3;      // 0..3
    const int lm   = lane >> 3;     // ldmatrix sub-matrix id 0..3
    const int lr8  = lane & 7;      // ldmatrix row-within-matrix
    const int net  = blockIdx.y;    // network k = net+1
    const int k    = net + 1;
    const int kt1  = (k + 15) >> 4; // causal trim of layer-1 k-tiles
    const int tile0 = blockIdx.x * 2;   // two 128-row tiles per CTA

    // ---- async bulk staging: both x halves + weights, two mbarriers ----
    if (t == 0) {
        MB_INIT(sb + SO_MB0, 1);
        MB_INIT(sb + SO_MB1, 1);
        const uint32_t w1b = (uint32_t)kt1 * 2048;   // only rows layer-1 reads
        MB_EXPECT(sb + SO_MB0, 16384 + w1b + 8192 + 2048);
        bulk_cp(sb + SO_XH0, gXH  + (size_t)tile0 * 16384, 16384, sb + SO_MB0);
        bulk_cp(sb + SO_W1,  gW1H + (size_t)net * 8192,  w1b, sb + SO_MB0);
        bulk_cp(sb + SO_W2,  gW2H + (size_t)net * 8192,  8192, sb + SO_MB0);
        bulk_cp(sb + SO_W3F, gW3F + (size_t)net * 2048,  2048, sb + SO_MB0);
        MB_EXPECT(sb + SO_MB1, 16384);
        bulk_cp(sb + SO_XH1, gXH + (size_t)(tile0 + 1) * 16384, 16384, sb + SO_MB1);
    }
    if (t < 64) {
        ((float*)(smc + SO_B1))[t] = B1[net * 64 + t];
        ((float*)(smc + SO_B2))[t] = B2[net * 64 + t];
    }
    if (t == 64)
        *((float2*)(smc + SO_B3)) = make_float2(B3[net * 2], B3[net * 2 + 1]);
    __syncthreads();

    const float* b1s = (const float*)(smc + SO_B1);
    const float* b2s = (const float*)(smc + SO_B2);
    const float2 b3  = *(const float2*)(smc + SO_B3);

    #define A_ADDR(xbase, m, kt) \
        (sb + (xbase) + SW((wrp * 32 + (m) * 16 + (lm & 1) * 8 + lr8) * 128 + (kt) * 32 + (lm >> 1) * 16))
    #define B_ADDR(base, kt, p) \
        (sb + (base) + SW(((kt) * 16 + (lm & 1) * 8 + lr8) * 128 + ((p) * 2 + (lm >> 1)) * 16))

    #pragma unroll 1
    for (int half = 0; half < 2; half++) {
        const uint32_t xbase = half ? SO_XH1 : SO_XH0;
        MB_WAIT(half ? (sb + SO_MB1) : (sb + SO_MB0), 0);
        const int brow0 = (tile0 + half) * TPB;

        // ====== layer 1: D1 = x[:, :k] @ W1 + B1 (single fp16 pass) ======
        float D1[2][8][4];          // [m][n-tile][frag]
        #pragma unroll
        for (int n = 0; n < 8; n++) {
            float bx = b1s[n * 8 + qc * 2], by = b1s[n * 8 + qc * 2 + 1];
            #pragma unroll
            for (int m = 0; m < 2; m++) {
                D1[m][n][0] = bx; D1[m][n][1] = by; D1[m][n][2] = bx; D1[m][n][3] = by;
            }
        }
        for (int kt = 0; kt < kt1; kt++) {
            uint32_t a[2][4];
            ldsm_x4(a[0], A_ADDR(xbase, 0, kt));
            ldsm_x4(a[1], A_ADDR(xbase, 1, kt));
            #pragma unroll
            for (int p = 0; p < 4; p++) {
                uint32_t bh[4];
                ldsm_x4t(bh, B_ADDR(SO_W1, kt, p));
                #pragma unroll
                for (int m = 0; m < 2; m++) {
                    mma16816(D1[m][2 * p],     a[m], bh[0], bh[1]);
                    mma16816(D1[m][2 * p + 1], a[m], bh[2], bh[3]);
                }
            }
        }

        // ---- relu + fp16-round D1 -> layer-2 A fragments ----
        uint32_t a2[4][2][4];       // [kt][m][frag]
        #pragma unroll
        for (int kt = 0; kt < 4; kt++) {
            #pragma unroll
            for (int m = 0; m < 2; m++) {
                a2[kt][m][0] = h2pack(fmaxf(D1[m][2*kt  ][0], 0.f), fmaxf(D1[m][2*kt  ][1], 0.f));
                a2[kt][m][1] = h2pack(fmaxf(D1[m][2*kt  ][2], 0.f), fmaxf(D1[m][2*kt  ][3], 0.f));
                a2[kt][m][2] = h2pack(fmaxf(D1[m][2*kt+1][0], 0.f), fmaxf(D1[m][2*kt+1][1], 0.f));
                a2[kt][m][3] = h2pack(fmaxf(D1[m][2*kt+1][2], 0.f), fmaxf(D1[m][2*kt+1][3], 0.f));
            }
        }

        // ====== layer 2 + MMA layer 3: n-pair p of L2 == k-tile p of L3 ======
        float D3[2][4];             // [m][frag]; cols 0,1 = (out0,out1)
        #pragma unroll
        for (int m = 0; m < 2; m++) {
            D3[m][0] = b3.x; D3[m][1] = b3.y; D3[m][2] = b3.x; D3[m][3] = b3.y;
        }
        #pragma unroll
        for (int p = 0; p < 4; p++) {
            float D2[2][2][4];       // [m][n-subtile][frag]
            #pragma unroll
            for (int q = 0; q < 2; q++) {
                int n = 2 * p + q;
                float bx = b2s[n * 8 + qc * 2], by = b2s[n * 8 + qc * 2 + 1];
                #pragma unroll
                for (int m = 0; m < 2; m++) {
                    D2[m][q][0] = bx; D2[m][q][1] = by; D2[m][q][2] = bx; D2[m][q][3] = by;
                }
            }
            #pragma unroll
            for (int kt = 0; kt < 4; kt++) {
                uint32_t bh[4];
                ldsm_x4t(bh, B_ADDR(SO_W2, kt, p));
                #pragma unroll
                for (int m = 0; m < 2; m++) {
                    mma16816(D2[m][0], a2[kt][m], bh[0], bh[1]);
                    mma16816(D2[m][1], a2[kt][m], bh[2], bh[3]);
                }
            }
            // relu + pack -> L3 A-fragment for k-tile p; fold into D3 via MMA
            uint32_t b3f[4];
            ldsm_x4t(b3f, sb + SO_W3F + (p * 16 + (lm & 1) * 8 + lr8) * 32 + (lm >> 1) * 16);
            #pragma unroll
            for (int m = 0; m < 2; m++) {
                uint32_t a3[4];
                a3[0] = h2pack(fmaxf(D2[m][0][0], 0.f), fmaxf(D2[m][0][1], 0.f));
                a3[1] = h2pack(fmaxf(D2[m][0][2], 0.f), fmaxf(D2[m][0][3], 0.f));
                a3[2] = h2pack(fmaxf(D2[m][1][0], 0.f), fmaxf(D2[m][1][1], 0.f));
                a3[3] = h2pack(fmaxf(D2[m][1][2], 0.f), fmaxf(D2[m][1][3], 0.f));
                mma16816(D3[m], a3, b3f[0], b3f[1]);
            }
        }

        // ---- store: qc==0 lanes hold cols 0,1 = (out0,out1) ----
        if (qc == 0) {
            #pragma unroll
            for (int m = 0; m < 2; m++) {
                int brow = brow0 + wrp * 32 + m * 16 + qr;
                out[(size_t)brow * 64 + k] = fminf(fmaxf(D3[m][0], -5.0f), 5.0f);
                out[(size_t)(BATCHN + brow) * 64 + k] = D3[m][1];
                out[(size_t)(brow + 8) * 64 + k] = fminf(fmaxf(D3[m][2], -5.0f), 5.0f);
                out[(size_t)(BATCHN + brow + 8) * 64 + k] = D3[m][3];
            }
        }

        // ---- network 0: constant column (net==0 CTAs only) ----
        if (net == 0) {
            float s0 = c0[0], t0 = c0[1];
            #pragma unroll
            for (int h = 0; h < 64; h++) {
                float hv = fmaxf(w0[h] + b0[h], 0.0f);
                s0 = fmaf(hv, v0[2 * h],     s0);
                t0 = fmaf(hv, v0[2 * h + 1], t0);
            }
            const int brow = brow0 + t;
            out[(size_t)brow * 64] = fminf(fmaxf(s0, -5.0f), 5.0f);
            out[(size_t)(BATCHN + brow) * 64] = t0;
        }
    }
}

extern "C" void kernel_launch(void* const* d_in, const int* in_sizes, int n_in,
                              void* d_out, int out_size)
{
    (void)in_sizes; (void)n_in; (void)out_size;
    const float* x  = (const float*)d_in[0];
    const float* w0 = (const float*)d_in[1];
    const float* b0 = (const float*)d_in[2];
    const float* v0 = (const float*)d_in[3];
    const float* c0 = (const float*)d_in[4];
    const float* W1 = (const float*)d_in[5];
    const float* B1 = (const float*)d_in[6];
    const float* W2 = (const float*)d_in[7];
    const float* B2 = (const float*)d_in[8];
    const float* W3 = (const float*)d_in[9];
    const float* B3 = (const float*)d_in[10];
    float* out = (float*)d_out;

    cudaFuncSetAttribute(arnet_hmma8,
                         cudaFuncAttributeMaxDynamicSharedMemorySize, SMEM_BYTES);

    prep_x<<<1024, TPB>>>(x);
    prep_w<<<63, TPB>>>(W1, W2, W3);
    dim3 grid(BATCHN / (2 * TPB), 63);   // (64, 63), 256 rows per CTA
    arnet_hmma8<<<grid, TPB, SMEM_BYTES>>>(w0, b0, v0, c0,
                                           B1, B2, B3, out);
}